// round 13
// baseline (speedup 1.0000x reference)
#include <cuda_runtime.h>
#include <math.h>

typedef unsigned long long ull;

#define Bn 4
#define Nn 512
#define Cc 256
#define Hh 8
#define Dd 32
#define DG 6
#define HID 16

// ---------------- scratch (device globals; no allocation) ----------------
__device__ float g_Q[Bn * Nn * Cc];
__device__ float g_K[Bn * Nn * Cc];   // row-compacted per batch
__device__ float g_V[Bn * Nn * Cc];   // row-compacted per batch (rows >= cnt stay 0)
__device__ float g_O[Bn * Nn * Cc];
__device__ float g_pre[(size_t)Bn * Hh * Nn * Nn];   // [b][h][n][cm] compacted cols
__device__ int   g_midx[Bn * Nn];                    // compacted -> real m
__device__ int   g_mpos[Bn * Nn];                    // real m -> compacted (or -1)
__device__ int   g_mcnt[Bn];                         // count per batch

// ---------------- packed f32x2 helpers ----------------
__device__ __forceinline__ ull pack2(float a, float b) {
    ull r; asm("mov.b64 %0, {%1,%2};" : "=l"(r) : "f"(a), "f"(b)); return r;
}
__device__ __forceinline__ void unpack2(ull v, float& a, float& b) {
    asm("mov.b64 {%0,%1}, %2;" : "=f"(a), "=f"(b) : "l"(v));
}
__device__ __forceinline__ ull fma2(ull a, ull b, ull c) {
    ull r; asm("fma.rn.f32x2 %0, %1, %2, %3;" : "=l"(r) : "l"(a), "l"(b), "l"(c)); return r;
}
__device__ __forceinline__ ull mul2(ull a, ull b) {
    ull r; asm("mul.rn.f32x2 %0, %1, %2;" : "=l"(r) : "l"(a), "l"(b)); return r;
}
__device__ __forceinline__ float tanh_ap(float x) {
    float r; asm("tanh.approx.f32 %0, %1;" : "=f"(r) : "f"(x)); return r;
}
__device__ __forceinline__ void lds2u64(ull& a, ull& b, unsigned addr) {
    asm volatile("ld.shared.v2.b64 {%0,%1}, [%2];" : "=l"(a), "=l"(b) : "r"(addr));
}
__device__ __forceinline__ ull lds1u64(unsigned addr) {
    ull a; asm volatile("ld.shared.b64 %0, [%1];" : "=l"(a) : "r"(addr)); return a;
}
__device__ __forceinline__ unsigned s2u(const void* p) {
    unsigned r;
    asm("{.reg .u64 t; cvta.to.shared.u64 t, %1; cvt.u32.u64 %0, t;}" : "=r"(r) : "l"(p));
    return r;
}
// swish(x) = 0.5x*tanh(0.5x) + 0.5x   (packed, 1 MUFU per lane)
__device__ __forceinline__ ull swish2(ull x, ull h2) {
    ull t = mul2(x, h2);
    float a, b; unpack2(t, a, b);
    ull th = pack2(tanh_ap(a), tanh_ap(b));
    return fma2(t, th, t);
}

// ---------------- mask compaction: one CTA per batch ----------------
__global__ void compact_mask_kernel(const int* __restrict__ mask,
                                    int* __restrict__ midx,
                                    int* __restrict__ mpos,
                                    int* __restrict__ mcnt) {
    __shared__ int wsum[16];
    int b = blockIdx.x;
    int t = threadIdx.x;            // 512 threads
    int lane = t & 31, wid = t >> 5;

    int v = mask[b * Nn + t] ? 1 : 0;
    unsigned bal = __ballot_sync(0xffffffff, v);
    int pre_in_warp = __popc(bal & ((1u << lane) - 1u));
    if (lane == 31) wsum[wid] = pre_in_warp + v;
    __syncthreads();
    if (t < 32) {
        int x = (t < 16) ? wsum[t] : 0;
        for (int off = 1; off < 16; off <<= 1) {
            int y = __shfl_up_sync(0xffffffff, x, off);
            if (lane >= off) x += y;
        }
        if (t < 16) wsum[t] = x;
    }
    __syncthreads();
    int base = (wid > 0 ? wsum[wid - 1] : 0);
    int p = base + pre_in_warp;
    mpos[b * Nn + t] = v ? p : -1;
    if (v) midx[b * Nn + p] = t;
    if (t == 511) mcnt[b] = wsum[15];
}

// ---------------- GEMM body: Y = X(Mx256) @ W(256x256) + bias ----------------
// 32x64 tile, 256 threads, 2x4 microtile. grid.y = M/32 (256 CTAs per GEMM).
// pos != nullptr: scatter output rows to compacted positions (skip masked).
__device__ __forceinline__ void gemm_body(const float* __restrict__ X,
                                          const float* __restrict__ W,
                                          const float* __restrict__ bias,
                                          float* __restrict__ Y,
                                          const int* __restrict__ pos) {
    __shared__ float As[16][36];   // As[k][m], padded
    __shared__ float Bs[16][68];   // Bs[k][n], padded

    int t  = threadIdx.x;
    int tx = t & 15;
    int ty = t >> 4;
    int m0 = blockIdx.y * 32;
    int n0 = blockIdx.x * 64;

    float acc[2][4];
#pragma unroll
    for (int i = 0; i < 2; i++)
#pragma unroll
        for (int j = 0; j < 4; j++) acc[i][j] = 0.0f;

    for (int k0 = 0; k0 < Cc; k0 += 16) {
        // load X tile 32x16 (transposed into As) -- first 128 threads
        if (t < 128) {
            int r = t >> 2;            // 0..31
            int c = (t & 3) << 2;      // 0,4,8,12
            float4 v = *(const float4*)&X[(size_t)(m0 + r) * Cc + k0 + c];
            As[c + 0][r] = v.x; As[c + 1][r] = v.y;
            As[c + 2][r] = v.z; As[c + 3][r] = v.w;
        }
        // load W tile 16x64 -- all 256 threads
        {
            int r = t >> 4;            // 0..15
            int c = (t & 15) << 2;     // 0..60
            *(float4*)&Bs[r][c] = *(const float4*)&W[(size_t)(k0 + r) * Cc + n0 + c];
        }
        __syncthreads();
#pragma unroll
        for (int k = 0; k < 16; k++) {
            float2 a = *(const float2*)&As[k][ty << 1];
            float b[4];
            *(float4*)b = *(const float4*)&Bs[k][tx << 2];
#pragma unroll
            for (int j = 0; j < 4; j++) {
                acc[0][j] = fmaf(a.x, b[j], acc[0][j]);
                acc[1][j] = fmaf(a.y, b[j], acc[1][j]);
            }
        }
        __syncthreads();
    }

    float4 bv = *(const float4*)&bias[n0 + (tx << 2)];
#pragma unroll
    for (int i = 0; i < 2; i++) {
        float4 o;
        o.x = acc[i][0] + bv.x; o.y = acc[i][1] + bv.y;
        o.z = acc[i][2] + bv.z; o.w = acc[i][3] + bv.w;
        int row = m0 + (ty << 1) + i;
        if (pos) {
            int p = pos[row];
            if (p < 0) continue;
            row = (row & ~(Nn - 1)) + p;
        }
        *(float4*)&Y[(size_t)row * Cc + n0 + (tx << 2)] = o;
    }
}

__global__ void gemm_qkv_kernel(const float* __restrict__ X,
                                const float* __restrict__ qw, const float* __restrict__ qb,
                                const float* __restrict__ kw, const float* __restrict__ kb,
                                const float* __restrict__ iw, const float* __restrict__ ib,
                                float* __restrict__ Qp, float* __restrict__ Kp,
                                float* __restrict__ Vp, const int* __restrict__ mpos) {
    if (blockIdx.z == 0)      gemm_body(X, qw, qb, Qp, nullptr);
    else if (blockIdx.z == 1) gemm_body(X, kw, kb, Kp, mpos);
    else                      gemm_body(X, iw, ib, Vp, mpos);
}

__global__ void gemm_out_kernel(const float* __restrict__ X,
                                const float* __restrict__ ow, const float* __restrict__ ob,
                                float* __restrict__ Yout) {
    gemm_body(X, ow, ob, Yout, nullptr);
}

// ---------------- logits over COMPACTED m (K compacted, pre compacted) ----------
#define LOGITS_SMEM_BYTES ((18768 + 32) * 4)

__global__ __launch_bounds__(128, 3)
void logits_kernel(const float* __restrict__ g,
                   const float* __restrict__ Q,
                   const float* __restrict__ K,
                   const float* __restrict__ w1, const float* __restrict__ b1,
                   const float* __restrict__ w2, const float* __restrict__ b2,
                   const float* __restrict__ w3, const float* __restrict__ b3,
                   const int* __restrict__ midx, const int* __restrict__ mcnt,
                   float* __restrict__ pre) {
    extern __shared__ float sm[];
    float*  Qs  = sm;
    float*  Kt  = sm + 4160;
    float2* w1d = (float2*)(sm + 12352);
    float2* w2d = (float2*)(sm + 13888);
    float2* w3d = (float2*)(sm + 17984);
    float2* b1d = (float2*)(sm + 18240);
    float2* b2d = (float2*)(sm + 18496);
    float2* b3d = (float2*)(sm + 18752);
    int*    mlist = (int*)(sm + 18768);

    int b  = blockIdx.z;
    int n0 = blockIdx.y * 16;
    int m0 = blockIdx.x * 32;           // compacted-column base
    int t  = threadIdx.x;

    int cnt = mcnt[b];
    if (m0 >= cnt) return;

    // real-m list for pairwise_g gather (clamped)
    if (t < 32) {
        int cm = m0 + t; if (cm > cnt - 1) cm = cnt - 1;
        mlist[t] = midx[b * Nn + cm];
    }

#pragma unroll
    for (int i = t; i < Hh * DG * HID; i += 128) { float v = w1[i]; w1d[i] = make_float2(v, v); }
#pragma unroll
    for (int i = t; i < Hh * HID * HID; i += 128){ float v = w2[i]; w2d[i] = make_float2(v, v); }
    {
        float v = w3[t]; w3d[t] = make_float2(v, v);
        float u = b1[t]; b1d[t] = make_float2(u, u);
        float z = b2[t]; b2d[t] = make_float2(z, z);
    }
    if (t < Hh) { float v = b3[t]; b3d[t] = make_float2(v, v); }

    // Q tile [16 n][256 c]
    {
        int r = t >> 3, c = (t & 7) << 5;
        const float* src = Q + (size_t)(b * Nn + n0 + r) * Cc + c;
#pragma unroll
        for (int v = 0; v < 8; v++)
            *(float4*)&Qs[r * 260 + c + v * 4] = *(const float4*)(src + v * 4);
    }
    // K tile transposed (K already row-compacted): Kt[c][cm-local]
#pragma unroll
    for (int bi = 0; bi < 4; bi++) {
        int blk = t + bi * 128;
        int bm = (blk & 7) << 2;
        int bc = (blk >> 3) << 2;
        int r0i = m0 + bm;     if (r0i > cnt - 1) r0i = cnt - 1;
        int r1i = m0 + bm + 1; if (r1i > cnt - 1) r1i = cnt - 1;
        int r2i = m0 + bm + 2; if (r2i > cnt - 1) r2i = cnt - 1;
        int r3i = m0 + bm + 3; if (r3i > cnt - 1) r3i = cnt - 1;
        float4 r0 = *(const float4*)&K[(size_t)(b * Nn + r0i) * Cc + bc];
        float4 r1 = *(const float4*)&K[(size_t)(b * Nn + r1i) * Cc + bc];
        float4 r2 = *(const float4*)&K[(size_t)(b * Nn + r2i) * Cc + bc];
        float4 r3 = *(const float4*)&K[(size_t)(b * Nn + r3i) * Cc + bc];
        *(float4*)&Kt[(bc + 0) * 32 + bm] = make_float4(r0.x, r1.x, r2.x, r3.x);
        *(float4*)&Kt[(bc + 1) * 32 + bm] = make_float4(r0.y, r1.y, r2.y, r3.y);
        *(float4*)&Kt[(bc + 2) * 32 + bm] = make_float4(r0.z, r1.z, r2.z, r3.z);
        *(float4*)&Kt[(bc + 3) * 32 + bm] = make_float4(r0.w, r1.w, r2.w, r3.w);
    }
    __syncthreads();

    int ni = t >> 4, mg = t & 15;
    int nr0 = n0 + 2 * ni;
    int cm0 = m0 + 2 * mg, cm1 = cm0 + 1;
    bool valid0 = cm0 < cnt, valid1 = cm1 < cnt;
    int mr0 = mlist[2 * mg];
    int mr1 = mlist[2 * mg + 1];

    // pairwise_g packed for both rows & both (gathered real) m's
    ull ga[6], gb[6];
    {
        const float* p00 = g + ((size_t)(b * Nn + nr0) * Nn + mr0) * DG;
        const float* p01 = g + ((size_t)(b * Nn + nr0) * Nn + mr1) * DG;
        const float* p10 = p00 + (size_t)Nn * DG;
        const float* p11 = p01 + (size_t)Nn * DG;
        float2 a0 = *(const float2*)(p00 + 0), a1 = *(const float2*)(p00 + 2), a2 = *(const float2*)(p00 + 4);
        float2 c0 = *(const float2*)(p01 + 0), c1 = *(const float2*)(p01 + 2), c2 = *(const float2*)(p01 + 4);
        ga[0] = pack2(a0.x, c0.x); ga[1] = pack2(a0.y, c0.y);
        ga[2] = pack2(a1.x, c1.x); ga[3] = pack2(a1.y, c1.y);
        ga[4] = pack2(a2.x, c2.x); ga[5] = pack2(a2.y, c2.y);
        float2 d0 = *(const float2*)(p10 + 0), d1 = *(const float2*)(p10 + 2), d2 = *(const float2*)(p10 + 4);
        float2 e0 = *(const float2*)(p11 + 0), e1 = *(const float2*)(p11 + 2), e2 = *(const float2*)(p11 + 4);
        gb[0] = pack2(d0.x, e0.x); gb[1] = pack2(d0.y, e0.y);
        gb[2] = pack2(d1.x, e1.x); gb[3] = pack2(d1.y, e1.y);
        gb[4] = pack2(d2.x, e2.x); gb[5] = pack2(d2.y, e2.y);
    }

    const ull h2 = pack2(0.5f, 0.5f);
    unsigned w1a = s2u(w1d), w2a = s2u(w2d), w3a = s2u(w3d);
    unsigned b1a = s2u(b1d), b2a = s2u(b2d), b3a = s2u(b3d);
    unsigned kta = s2u(Kt) + mg * 8;

#pragma unroll 1
    for (int h = 0; h < Hh; h++) {
        ull x0[16], x1[16];
        {
            unsigned ba = b1a + h * 128;
#pragma unroll
            for (int j = 0; j < 16; j += 2) {
                lds2u64(x0[j], x0[j + 1], ba + j * 8);
                x1[j] = x0[j]; x1[j + 1] = x0[j + 1];
            }
        }
#pragma unroll
        for (int k = 0; k < DG; k++) {
            unsigned wa = w1a + (h * DG + k) * 128;
#pragma unroll
            for (int j = 0; j < 16; j += 2) {
                ull wlo, whi; lds2u64(wlo, whi, wa + j * 8);
                x0[j]     = fma2(ga[k], wlo, x0[j]);
                x0[j + 1] = fma2(ga[k], whi, x0[j + 1]);
                x1[j]     = fma2(gb[k], wlo, x1[j]);
                x1[j + 1] = fma2(gb[k], whi, x1[j + 1]);
            }
        }
#pragma unroll
        for (int j = 0; j < 16; j++) { x0[j] = swish2(x0[j], h2); x1[j] = swish2(x1[j], h2); }

        ull a30 = lds1u64(b3a + h * 8);
        ull a31 = a30;
#pragma unroll
        for (int jh = 0; jh < 2; jh++) {
            ull y0[8], y1[8];
            unsigned ba = b2a + h * 128 + jh * 64;
#pragma unroll
            for (int j = 0; j < 8; j += 2) {
                lds2u64(y0[j], y0[j + 1], ba + j * 8);
                y1[j] = y0[j]; y1[j + 1] = y0[j + 1];
            }
#pragma unroll
            for (int k = 0; k < HID; k++) {
                unsigned wa = w2a + (h * HID + k) * 128 + jh * 64;
#pragma unroll
                for (int j = 0; j < 8; j += 2) {
                    ull wlo, whi; lds2u64(wlo, whi, wa + j * 8);
                    y0[j]     = fma2(x0[k], wlo, y0[j]);
                    y0[j + 1] = fma2(x0[k], whi, y0[j + 1]);
                    y1[j]     = fma2(x1[k], wlo, y1[j]);
                    y1[j + 1] = fma2(x1[k], whi, y1[j + 1]);
                }
            }
#pragma unroll
            for (int j = 0; j < 8; j++) { y0[j] = swish2(y0[j], h2); y1[j] = swish2(y1[j], h2); }
#pragma unroll
            for (int j = 0; j < 8; j += 2) {
                ull wlo, whi; lds2u64(wlo, whi, w3a + h * 128 + jh * 64 + j * 8);
                a30 = fma2(y0[j], wlo, a30); a30 = fma2(y0[j + 1], whi, a30);
                a31 = fma2(y1[j], wlo, a31); a31 = fma2(y1[j + 1], whi, a31);
            }
        }
        ull aloc0 = swish2(a30, h2);
        ull aloc1 = swish2(a31, h2);

        ull af0 = pack2(0.0f, 0.0f), af1 = af0;
        unsigned kh = kta + (h * 32) * 128;
#pragma unroll
        for (int cc = 0; cc < 32; cc += 4) {
            float4 q0 = *(const float4*)&Qs[(2 * ni) * 260 + h * 32 + cc];
            float4 q1 = *(const float4*)&Qs[(2 * ni + 1) * 260 + h * 32 + cc];
            ull k0 = lds1u64(kh + (cc + 0) * 128);
            ull k1 = lds1u64(kh + (cc + 1) * 128);
            ull k2 = lds1u64(kh + (cc + 2) * 128);
            ull k3 = lds1u64(kh + (cc + 3) * 128);
            af0 = fma2(k0, pack2(q0.x, q0.x), af0);
            af0 = fma2(k1, pack2(q0.y, q0.y), af0);
            af0 = fma2(k2, pack2(q0.z, q0.z), af0);
            af0 = fma2(k3, pack2(q0.w, q0.w), af0);
            af1 = fma2(k0, pack2(q1.x, q1.x), af1);
            af1 = fma2(k1, pack2(q1.y, q1.y), af1);
            af1 = fma2(k2, pack2(q1.z, q1.z), af1);
            af1 = fma2(k3, pack2(q1.w, q1.w), af1);
        }

        float a0, a1, l0, l1;
        float* pr = pre + ((size_t)(b * Hh + h) * Nn + nr0) * Nn;
        unpack2(af0, a0, a1); unpack2(aloc0, l0, l1);
        if (valid1)      *(float2*)&pr[cm0] = make_float2(l0 + a0 * 0.0625f, l1 + a1 * 0.0625f);
        else if (valid0) pr[cm0] = l0 + a0 * 0.0625f;
        unpack2(af1, a0, a1); unpack2(aloc1, l0, l1);
        if (valid1)      *(float2*)&pr[Nn + cm0] = make_float2(l0 + a0 * 0.0625f, l1 + a1 * 0.0625f);
        else if (valid0) pr[Nn + cm0] = l0 + a0 * 0.0625f;
    }
}

// ---------------- softmax + att@V, V tile staged in smem ----------------
#define SOFTMAX_SMEM_BYTES (18000 * 4)

__global__ __launch_bounds__(256)
void softmax_av_kernel(const float* __restrict__ pre,
                       const float* __restrict__ V,
                       const int* __restrict__ mcnt,
                       float* __restrict__ out) {
    extern __shared__ float sm2[];
    float*  att  = sm2;                      // [16][516]
    float*  Vs   = sm2 + 8256;               // [256][32]
    float4* part = (float4*)(sm2 + 16448);   // [3][16][8]
    float*  rinv = sm2 + 17984;              // [16]

    int b  = blockIdx.z;
    int h  = blockIdx.y;
    int n0 = blockIdx.x * 16;
    int t  = threadIdx.x;
    int row = t >> 4;
    int l16 = t & 15;

    int cnt  = mcnt[b];
    int jmax = (cnt + 63) >> 6;

    const float4* prow = (const float4*)(pre + ((size_t)(b * Hh + h) * Nn + n0 + row) * Nn);
    float* arow = att + row * 516;

    float mx = -3.0e38f;
    for (int j = 0; j < jmax; j++) {
        int i4 = j * 16 + l16;
        int m4 = i4 * 4;
        float4 v = prow[i4];
        if (m4 + 0 >= cnt) v.x = -1e38f;
        if (m4 + 1 >= cnt) v.y = -1e38f;
        if (m4 + 2 >= cnt) v.z = -1e38f;
        if (m4 + 3 >= cnt) v.w = -1e38f;
        *(float4*)&arow[m4] = v;
        mx = fmaxf(mx, fmaxf(fmaxf(v.x, v.y), fmaxf(v.z, v.w)));
    }
    mx = fmaxf(mx, __shfl_xor_sync(0xffffffff, mx, 1));
    mx = fmaxf(mx, __shfl_xor_sync(0xffffffff, mx, 2));
    mx = fmaxf(mx, __shfl_xor_sync(0xffffffff, mx, 4));
    mx = fmaxf(mx, __shfl_xor_sync(0xffffffff, mx, 8));

    float s = 0.0f;
    for (int j = 0; j < jmax; j++) {
        int m4 = (j * 16 + l16) * 4;
        float4 v = *(const float4*)&arow[m4];
        float4 e;
        e.x = __expf(v.x - mx); e.y = __expf(v.y - mx);
        e.z = __expf(v.z - mx); e.w = __expf(v.w - mx);
        s += e.x + e.y + e.z + e.w;
        *(float4*)&arow[m4] = e;
    }
    s += __shfl_xor_sync(0xffffffff, s, 1);
    s += __shfl_xor_sync(0xffffffff, s, 2);
    s += __shfl_xor_sync(0xffffffff, s, 4);
    s += __shfl_xor_sync(0xffffffff, s, 8);
    if (l16 == 0) rinv[row] = __fdividef(1.0f, s);

    int cntP = (cnt + 15) & ~15;
    int rp = t >> 5;
    int q  = (t >> 3) & 3;
    int dq = t & 7;
    int row0 = rp * 2;
    const float* a0row = att + (size_t)row0 * 516;
    const float* a1row = a0row + 516;
    const float* vbase = V + (size_t)b * Nn * Cc + h * Dd;

    float4 acc0 = make_float4(0.f, 0.f, 0.f, 0.f);
    float4 acc1 = make_float4(0.f, 0.f, 0.f, 0.f);

    for (int c0 = 0; c0 < cntP; c0 += 256) {
        __syncthreads();
#pragma unroll
        for (int pass = 0; pass < 8; pass++) {
            int lr = pass * 32 + (t >> 3);
            float4 v = *(const float4*)(vbase + (size_t)(c0 + lr) * Cc + ((t & 7) << 2));
            *(float4*)&Vs[lr * 32 + ((t & 7) << 2)] = v;
        }
        __syncthreads();

        int chunkLen = cntP - c0; if (chunkLen > 256) chunkLen = 256;
        int qLen = chunkLen >> 2;
        int mbase = q * qLen;
#pragma unroll 2
        for (int mm = 0; mm < qLen; mm += 4) {
            int ml = mbase + mm;
            int mg = c0 + ml;
            float4 a4 = *(const float4*)&a0row[mg];
            float4 b4 = *(const float4*)&a1row[mg];
            float4 v0 = *(const float4*)&Vs[(ml + 0) * 32 + (dq << 2)];
            float4 v1 = *(const float4*)&Vs[(ml + 1) * 32 + (dq << 2)];
            float4 v2 = *(const float4*)&Vs[(ml + 2) * 32 + (dq << 2)];
            float4 v3 = *(const float4*)&Vs[(ml + 3) * 32 + (dq << 2)];
            acc0.x = fmaf(a4.x, v0.x, acc0.x); acc0.y = fmaf(a4.x, v0.y, acc0.y);
            acc0.z = fmaf(a4.x, v0.z, acc0.z); acc0.w = fmaf(a4.x, v0.w, acc0.w);
            acc1.x = fmaf(b4.x, v0.x, acc1.x); acc1.y = fmaf(b4.x, v0.y, acc1.y);
            acc1.z = fmaf(b4.x, v0.z, acc1.z); acc1.w = fmaf(b4.x, v0.w, acc1.w);
            acc0.x = fmaf(a4.y, v1.x, acc0.x); acc0.y = fmaf(a4.y, v1.y, acc0.y);
            acc0.z = fmaf(a4.y, v1.z, acc0.z); acc0.w = fmaf(a4.y, v1.w, acc0.w);
            acc1.x = fmaf(b4.y, v1.x, acc1.x); acc1.y = fmaf(b4.y, v1.y, acc1.y);
            acc1.z = fmaf(b4.y, v1.z, acc1.z); acc1.w = fmaf(b4.y, v1.w, acc1.w);
            acc0.x = fmaf(a4.z, v2.x, acc0.x); acc0.y = fmaf(a4.z, v2.y, acc0.y);
            acc0.z = fmaf(a4.z, v2.z, acc0.z); acc0.w = fmaf(a4.z, v2.w, acc0.w);
            acc1.x = fmaf(b4.z, v2.x, acc1.x); acc1.y = fmaf(b4.z, v2.y, acc1.y);
            acc1.z = fmaf(b4.z, v2.z, acc1.z); acc1.w = fmaf(b4.z, v2.w, acc1.w);
            acc0.x = fmaf(a4.w, v3.x, acc0.x); acc0.y = fmaf(a4.w, v3.y, acc0.y);
            acc0.z = fmaf(a4.w, v3.z, acc0.z); acc0.w = fmaf(a4.w, v3.w, acc0.w);
            acc1.x = fmaf(b4.w, v3.x, acc1.x); acc1.y = fmaf(b4.w, v3.y, acc1.y);
            acc1.z = fmaf(b4.w, v3.z, acc1.z); acc1.w = fmaf(b4.w, v3.w, acc1.w);
        }
    }

    if (q > 0) {
        part[((q - 1) * 16 + row0) * 8 + dq] = acc0;
        part[((q - 1) * 16 + row0 + 1) * 8 + dq] = acc1;
    }
    __syncthreads();

    if (q == 0) {
        float iv0 = rinv[row0];
        float iv1 = rinv[row0 + 1];
#pragma unroll
        for (int pq = 0; pq < 3; pq++) {
            float4 p0 = part[(pq * 16 + row0) * 8 + dq];
            float4 p1 = part[(pq * 16 + row0 + 1) * 8 + dq];
            acc0.x += p0.x; acc0.y += p0.y; acc0.z += p0.z; acc0.w += p0.w;
            acc1.x += p1.x; acc1.y += p1.y; acc1.z += p1.z; acc1.w += p1.w;
        }
        acc0.x *= iv0; acc0.y *= iv0; acc0.z *= iv0; acc0.w *= iv0;
        acc1.x *= iv1; acc1.y *= iv1; acc1.z *= iv1; acc1.w *= iv1;
        *(float4*)&out[(size_t)(b * Nn + n0 + row0) * Cc + h * Dd + (dq << 2)] = acc0;
        *(float4*)&out[(size_t)(b * Nn + n0 + row0 + 1) * Cc + h * Dd + (dq << 2)] = acc1;
    }
}

// ---------------- launch ----------------
extern "C" void kernel_launch(void* const* d_in, const int* in_sizes, int n_in,
                              void* d_out, int out_size) {
    const float* pg = (const float*)d_in[0];
    const float* cs = (const float*)d_in[1];
    const float* qw = (const float*)d_in[2];
    const float* qb = (const float*)d_in[3];
    const float* kw = (const float*)d_in[4];
    const float* kb = (const float*)d_in[5];
    const float* iw = (const float*)d_in[6];
    const float* ib = (const float*)d_in[7];
    const float* ow = (const float*)d_in[8];
    const float* ob = (const float*)d_in[9];
    const float* w1 = (const float*)d_in[10];
    const float* b1 = (const float*)d_in[11];
    const float* w2 = (const float*)d_in[12];
    const float* b2 = (const float*)d_in[13];
    const float* w3 = (const float*)d_in[14];
    const float* b3 = (const float*)d_in[15];
    const int*  mask = (const int*)d_in[16];

    float *Qp, *Kp, *Vp, *Op, *Pp;
    int *MIp, *MPp, *MCp;
    cudaGetSymbolAddress((void**)&Qp, g_Q);
    cudaGetSymbolAddress((void**)&Kp, g_K);
    cudaGetSymbolAddress((void**)&Vp, g_V);
    cudaGetSymbolAddress((void**)&Op, g_O);
    cudaGetSymbolAddress((void**)&Pp, g_pre);
    cudaGetSymbolAddress((void**)&MIp, g_midx);
    cudaGetSymbolAddress((void**)&MPp, g_mpos);
    cudaGetSymbolAddress((void**)&MCp, g_mcnt);

    cudaFuncSetAttribute(logits_kernel,
                         cudaFuncAttributeMaxDynamicSharedMemorySize,
                         LOGITS_SMEM_BYTES);
    cudaFuncSetAttribute(softmax_av_kernel,
                         cudaFuncAttributeMaxDynamicSharedMemorySize,
                         SOFTMAX_SMEM_BYTES);

    const int M = Bn * Nn;   // 2048

    compact_mask_kernel<<<Bn, 512>>>(mask, MIp, MPp, MCp);

    gemm_qkv_kernel<<<dim3(Cc / 64, M / 32, 3), 256>>>(cs, qw, qb, kw, kb, iw, ib,
                                                       Qp, Kp, Vp, MPp);

    logits_kernel<<<dim3(Nn / 32, Nn / 16, Bn), 128, LOGITS_SMEM_BYTES>>>(
        pg, Qp, Kp, w1, b1, w2, b2, w3, b3, MIp, MCp, Pp);

    softmax_av_kernel<<<dim3(Nn / 16, Hh, Bn), 256, SOFTMAX_SMEM_BYTES>>>(
        Pp, Vp, MCp, Op);

    gemm_out_kernel<<<dim3(Cc / 64, M / 32), 256>>>(Op, ow, ob, (float*)d_out);
}

// round 14
// speedup vs baseline: 1.1262x; 1.1262x over previous
#include <cuda_runtime.h>
#include <math.h>

typedef unsigned long long ull;

#define Bn 4
#define Nn 512
#define Cc 256
#define Hh 8
#define Dd 32
#define DG 6
#define HID 16

// ---------------- scratch (device globals; no allocation) ----------------
__device__ float g_Q[Bn * Nn * Cc];
__device__ float g_K[Bn * Nn * Cc];   // row-compacted per batch
__device__ float g_V[Bn * Nn * Cc];   // row-compacted per batch (rows >= cnt stay 0)
__device__ float g_O[Bn * Nn * Cc];
__device__ float g_pre[(size_t)Bn * Hh * Nn * Nn];   // [b][h][n][cm] compacted cols
__device__ int   g_midx[Bn * Nn];                    // compacted -> real m
__device__ int   g_mpos[Bn * Nn];                    // real m -> compacted (or -1)
__device__ int   g_mcnt[Bn];                         // count per batch

// ---------------- packed f32x2 helpers ----------------
__device__ __forceinline__ ull pack2(float a, float b) {
    ull r; asm("mov.b64 %0, {%1,%2};" : "=l"(r) : "f"(a), "f"(b)); return r;
}
__device__ __forceinline__ void unpack2(ull v, float& a, float& b) {
    asm("mov.b64 {%0,%1}, %2;" : "=f"(a), "=f"(b) : "l"(v));
}
__device__ __forceinline__ ull fma2(ull a, ull b, ull c) {
    ull r; asm("fma.rn.f32x2 %0, %1, %2, %3;" : "=l"(r) : "l"(a), "l"(b), "l"(c)); return r;
}
__device__ __forceinline__ ull mul2(ull a, ull b) {
    ull r; asm("mul.rn.f32x2 %0, %1, %2;" : "=l"(r) : "l"(a), "l"(b)); return r;
}
__device__ __forceinline__ float tanh_ap(float x) {
    float r; asm("tanh.approx.f32 %0, %1;" : "=f"(r) : "f"(x)); return r;
}
__device__ __forceinline__ void lds2u64(ull& a, ull& b, unsigned addr) {
    asm volatile("ld.shared.v2.b64 {%0,%1}, [%2];" : "=l"(a), "=l"(b) : "r"(addr));
}
__device__ __forceinline__ ull lds1u64(unsigned addr) {
    ull a; asm volatile("ld.shared.b64 %0, [%1];" : "=l"(a) : "r"(addr)); return a;
}
__device__ __forceinline__ unsigned s2u(const void* p) {
    unsigned r;
    asm("{.reg .u64 t; cvta.to.shared.u64 t, %1; cvt.u32.u64 %0, t;}" : "=r"(r) : "l"(p));
    return r;
}
// swish(x) = 0.5x*tanh(0.5x) + 0.5x   (packed, 1 MUFU per lane)
__device__ __forceinline__ ull swish2(ull x, ull h2) {
    ull t = mul2(x, h2);
    float a, b; unpack2(t, a, b);
    ull th = pack2(tanh_ap(a), tanh_ap(b));
    return fma2(t, th, t);
}

// ---------------- mask compaction: one CTA per batch ----------------
__global__ void compact_mask_kernel(const int* __restrict__ mask,
                                    int* __restrict__ midx,
                                    int* __restrict__ mpos,
                                    int* __restrict__ mcnt) {
    __shared__ int wsum[16];
    int b = blockIdx.x;
    int t = threadIdx.x;            // 512 threads
    int lane = t & 31, wid = t >> 5;

    int v = mask[b * Nn + t] ? 1 : 0;
    unsigned bal = __ballot_sync(0xffffffff, v);
    int pre_in_warp = __popc(bal & ((1u << lane) - 1u));
    if (lane == 31) wsum[wid] = pre_in_warp + v;
    __syncthreads();
    if (t < 32) {
        int x = (t < 16) ? wsum[t] : 0;
        for (int off = 1; off < 16; off <<= 1) {
            int y = __shfl_up_sync(0xffffffff, x, off);
            if (lane >= off) x += y;
        }
        if (t < 16) wsum[t] = x;
    }
    __syncthreads();
    int base = (wid > 0 ? wsum[wid - 1] : 0);
    int p = base + pre_in_warp;
    mpos[b * Nn + t] = v ? p : -1;
    if (v) midx[b * Nn + p] = t;
    if (t == 511) mcnt[b] = wsum[15];
}

// ---------------- GEMM body: Y = X(Mx256) @ W(256x256) + bias ----------------
// 64x64 tile, 256 threads, 4x4 microtile, register-prefetch software pipeline.
// pos != nullptr: scatter output rows to compacted positions (skip masked).
__device__ __forceinline__ void gemm_body(const float* __restrict__ X,
                                          const float* __restrict__ W,
                                          const float* __restrict__ bias,
                                          float* __restrict__ Y,
                                          const int* __restrict__ pos) {
    __shared__ float As[16][68];   // As[k][m], padded
    __shared__ float Bs[16][68];   // Bs[k][n], padded

    int t  = threadIdx.x;
    int tx = t & 15;
    int ty = t >> 4;
    int m0 = blockIdx.y * 64;
    int n0 = blockIdx.x * 64;

    // per-thread load coords
    int xr = t >> 2;            // 0..63 (X row)
    int xc = (t & 3) << 2;      // 0,4,8,12 (X col within BK)
    int wr = t >> 4;            // 0..15 (W row within BK)
    int wc = (t & 15) << 2;     // 0..60 (W col)
    const float* xptr = &X[(size_t)(m0 + xr) * Cc + xc];
    const float* wptr = &W[(size_t)wr * Cc + n0 + wc];

    float acc[4][4];
#pragma unroll
    for (int i = 0; i < 4; i++)
#pragma unroll
        for (int j = 0; j < 4; j++) acc[i][j] = 0.0f;

    // preload tile 0
    float4 xv = *(const float4*)xptr;
    float4 wv = *(const float4*)wptr;
    As[xc + 0][xr] = xv.x; As[xc + 1][xr] = xv.y;
    As[xc + 2][xr] = xv.z; As[xc + 3][xr] = xv.w;
    *(float4*)&Bs[wr][wc] = wv;
    __syncthreads();

#pragma unroll 1
    for (int k0 = 16; k0 < Cc; k0 += 16) {
        // issue next tile's loads (latency overlapped with compute below)
        xv = *(const float4*)(xptr + k0);
        wv = *(const float4*)(wptr + (size_t)k0 * Cc);

#pragma unroll
        for (int k = 0; k < 16; k++) {
            float a[4], b[4];
            *(float4*)a = *(const float4*)&As[k][ty << 2];
            *(float4*)b = *(const float4*)&Bs[k][tx << 2];
#pragma unroll
            for (int i = 0; i < 4; i++)
#pragma unroll
                for (int j = 0; j < 4; j++) acc[i][j] = fmaf(a[i], b[j], acc[i][j]);
        }
        __syncthreads();
        As[xc + 0][xr] = xv.x; As[xc + 1][xr] = xv.y;
        As[xc + 2][xr] = xv.z; As[xc + 3][xr] = xv.w;
        *(float4*)&Bs[wr][wc] = wv;
        __syncthreads();
    }
    // last tile
#pragma unroll
    for (int k = 0; k < 16; k++) {
        float a[4], b[4];
        *(float4*)a = *(const float4*)&As[k][ty << 2];
        *(float4*)b = *(const float4*)&Bs[k][tx << 2];
#pragma unroll
        for (int i = 0; i < 4; i++)
#pragma unroll
            for (int j = 0; j < 4; j++) acc[i][j] = fmaf(a[i], b[j], acc[i][j]);
    }

    float4 bv = *(const float4*)&bias[n0 + (tx << 2)];
#pragma unroll
    for (int i = 0; i < 4; i++) {
        float4 o;
        o.x = acc[i][0] + bv.x; o.y = acc[i][1] + bv.y;
        o.z = acc[i][2] + bv.z; o.w = acc[i][3] + bv.w;
        int row = m0 + (ty << 2) + i;
        if (pos) {
            int p = pos[row];
            if (p < 0) continue;
            row = (row & ~(Nn - 1)) + p;
        }
        *(float4*)&Y[(size_t)row * Cc + n0 + (tx << 2)] = o;
    }
}

__global__ void gemm_qkv_kernel(const float* __restrict__ X,
                                const float* __restrict__ qw, const float* __restrict__ qb,
                                const float* __restrict__ kw, const float* __restrict__ kb,
                                const float* __restrict__ iw, const float* __restrict__ ib,
                                float* __restrict__ Qp, float* __restrict__ Kp,
                                float* __restrict__ Vp, const int* __restrict__ mpos) {
    if (blockIdx.z == 0)      gemm_body(X, qw, qb, Qp, nullptr);
    else if (blockIdx.z == 1) gemm_body(X, kw, kb, Kp, mpos);
    else                      gemm_body(X, iw, ib, Vp, mpos);
}

__global__ void gemm_out_kernel(const float* __restrict__ X,
                                const float* __restrict__ ow, const float* __restrict__ ob,
                                float* __restrict__ Yout) {
    gemm_body(X, ow, ob, Yout, nullptr);
}

// ---------------- logits over COMPACTED m (K compacted, pre compacted) ----------
#define LOGITS_SMEM_BYTES ((18768 + 32) * 4)

__global__ __launch_bounds__(128, 3)
void logits_kernel(const float* __restrict__ g,
                   const float* __restrict__ Q,
                   const float* __restrict__ K,
                   const float* __restrict__ w1, const float* __restrict__ b1,
                   const float* __restrict__ w2, const float* __restrict__ b2,
                   const float* __restrict__ w3, const float* __restrict__ b3,
                   const int* __restrict__ midx, const int* __restrict__ mcnt,
                   float* __restrict__ pre) {
    extern __shared__ float sm[];
    float*  Qs  = sm;
    float*  Kt  = sm + 4160;
    float2* w1d = (float2*)(sm + 12352);
    float2* w2d = (float2*)(sm + 13888);
    float2* w3d = (float2*)(sm + 17984);
    float2* b1d = (float2*)(sm + 18240);
    float2* b2d = (float2*)(sm + 18496);
    float2* b3d = (float2*)(sm + 18752);
    int*    mlist = (int*)(sm + 18768);

    int b  = blockIdx.z;
    int n0 = blockIdx.y * 16;
    int m0 = blockIdx.x * 32;           // compacted-column base
    int t  = threadIdx.x;

    int cnt = mcnt[b];
    if (m0 >= cnt) return;

    // real-m list for pairwise_g gather (clamped)
    if (t < 32) {
        int cm = m0 + t; if (cm > cnt - 1) cm = cnt - 1;
        mlist[t] = midx[b * Nn + cm];
    }

#pragma unroll
    for (int i = t; i < Hh * DG * HID; i += 128) { float v = w1[i]; w1d[i] = make_float2(v, v); }
#pragma unroll
    for (int i = t; i < Hh * HID * HID; i += 128){ float v = w2[i]; w2d[i] = make_float2(v, v); }
    {
        float v = w3[t]; w3d[t] = make_float2(v, v);
        float u = b1[t]; b1d[t] = make_float2(u, u);
        float z = b2[t]; b2d[t] = make_float2(z, z);
    }
    if (t < Hh) { float v = b3[t]; b3d[t] = make_float2(v, v); }

    // Q tile [16 n][256 c]
    {
        int r = t >> 3, c = (t & 7) << 5;
        const float* src = Q + (size_t)(b * Nn + n0 + r) * Cc + c;
#pragma unroll
        for (int v = 0; v < 8; v++)
            *(float4*)&Qs[r * 260 + c + v * 4] = *(const float4*)(src + v * 4);
    }
    // K tile transposed (K already row-compacted): Kt[c][cm-local]
#pragma unroll
    for (int bi = 0; bi < 4; bi++) {
        int blk = t + bi * 128;
        int bm = (blk & 7) << 2;
        int bc = (blk >> 3) << 2;
        int r0i = m0 + bm;     if (r0i > cnt - 1) r0i = cnt - 1;
        int r1i = m0 + bm + 1; if (r1i > cnt - 1) r1i = cnt - 1;
        int r2i = m0 + bm + 2; if (r2i > cnt - 1) r2i = cnt - 1;
        int r3i = m0 + bm + 3; if (r3i > cnt - 1) r3i = cnt - 1;
        float4 r0 = *(const float4*)&K[(size_t)(b * Nn + r0i) * Cc + bc];
        float4 r1 = *(const float4*)&K[(size_t)(b * Nn + r1i) * Cc + bc];
        float4 r2 = *(const float4*)&K[(size_t)(b * Nn + r2i) * Cc + bc];
        float4 r3 = *(const float4*)&K[(size_t)(b * Nn + r3i) * Cc + bc];
        *(float4*)&Kt[(bc + 0) * 32 + bm] = make_float4(r0.x, r1.x, r2.x, r3.x);
        *(float4*)&Kt[(bc + 1) * 32 + bm] = make_float4(r0.y, r1.y, r2.y, r3.y);
        *(float4*)&Kt[(bc + 2) * 32 + bm] = make_float4(r0.z, r1.z, r2.z, r3.z);
        *(float4*)&Kt[(bc + 3) * 32 + bm] = make_float4(r0.w, r1.w, r2.w, r3.w);
    }
    __syncthreads();

    int ni = t >> 4, mg = t & 15;
    int nr0 = n0 + 2 * ni;
    int cm0 = m0 + 2 * mg, cm1 = cm0 + 1;
    bool valid0 = cm0 < cnt, valid1 = cm1 < cnt;
    int mr0 = mlist[2 * mg];
    int mr1 = mlist[2 * mg + 1];

    // pairwise_g packed for both rows & both (gathered real) m's
    ull ga[6], gb[6];
    {
        const float* p00 = g + ((size_t)(b * Nn + nr0) * Nn + mr0) * DG;
        const float* p01 = g + ((size_t)(b * Nn + nr0) * Nn + mr1) * DG;
        const float* p10 = p00 + (size_t)Nn * DG;
        const float* p11 = p01 + (size_t)Nn * DG;
        float2 a0 = *(const float2*)(p00 + 0), a1 = *(const float2*)(p00 + 2), a2 = *(const float2*)(p00 + 4);
        float2 c0 = *(const float2*)(p01 + 0), c1 = *(const float2*)(p01 + 2), c2 = *(const float2*)(p01 + 4);
        ga[0] = pack2(a0.x, c0.x); ga[1] = pack2(a0.y, c0.y);
        ga[2] = pack2(a1.x, c1.x); ga[3] = pack2(a1.y, c1.y);
        ga[4] = pack2(a2.x, c2.x); ga[5] = pack2(a2.y, c2.y);
        float2 d0 = *(const float2*)(p10 + 0), d1 = *(const float2*)(p10 + 2), d2 = *(const float2*)(p10 + 4);
        float2 e0 = *(const float2*)(p11 + 0), e1 = *(const float2*)(p11 + 2), e2 = *(const float2*)(p11 + 4);
        gb[0] = pack2(d0.x, e0.x); gb[1] = pack2(d0.y, e0.y);
        gb[2] = pack2(d1.x, e1.x); gb[3] = pack2(d1.y, e1.y);
        gb[4] = pack2(d2.x, e2.x); gb[5] = pack2(d2.y, e2.y);
    }

    const ull h2 = pack2(0.5f, 0.5f);
    unsigned w1a = s2u(w1d), w2a = s2u(w2d), w3a = s2u(w3d);
    unsigned b1a = s2u(b1d), b2a = s2u(b2d), b3a = s2u(b3d);
    unsigned kta = s2u(Kt) + mg * 8;

#pragma unroll 1
    for (int h = 0; h < Hh; h++) {
        ull x0[16], x1[16];
        {
            unsigned ba = b1a + h * 128;
#pragma unroll
            for (int j = 0; j < 16; j += 2) {
                lds2u64(x0[j], x0[j + 1], ba + j * 8);
                x1[j] = x0[j]; x1[j + 1] = x0[j + 1];
            }
        }
#pragma unroll
        for (int k = 0; k < DG; k++) {
            unsigned wa = w1a + (h * DG + k) * 128;
#pragma unroll
            for (int j = 0; j < 16; j += 2) {
                ull wlo, whi; lds2u64(wlo, whi, wa + j * 8);
                x0[j]     = fma2(ga[k], wlo, x0[j]);
                x0[j + 1] = fma2(ga[k], whi, x0[j + 1]);
                x1[j]     = fma2(gb[k], wlo, x1[j]);
                x1[j + 1] = fma2(gb[k], whi, x1[j + 1]);
            }
        }
#pragma unroll
        for (int j = 0; j < 16; j++) { x0[j] = swish2(x0[j], h2); x1[j] = swish2(x1[j], h2); }

        ull a30 = lds1u64(b3a + h * 8);
        ull a31 = a30;
#pragma unroll
        for (int jh = 0; jh < 2; jh++) {
            ull y0[8], y1[8];
            unsigned ba = b2a + h * 128 + jh * 64;
#pragma unroll
            for (int j = 0; j < 8; j += 2) {
                lds2u64(y0[j], y0[j + 1], ba + j * 8);
                y1[j] = y0[j]; y1[j + 1] = y0[j + 1];
            }
#pragma unroll
            for (int k = 0; k < HID; k++) {
                unsigned wa = w2a + (h * HID + k) * 128 + jh * 64;
#pragma unroll
                for (int j = 0; j < 8; j += 2) {
                    ull wlo, whi; lds2u64(wlo, whi, wa + j * 8);
                    y0[j]     = fma2(x0[k], wlo, y0[j]);
                    y0[j + 1] = fma2(x0[k], whi, y0[j + 1]);
                    y1[j]     = fma2(x1[k], wlo, y1[j]);
                    y1[j + 1] = fma2(x1[k], whi, y1[j + 1]);
                }
            }
#pragma unroll
            for (int j = 0; j < 8; j++) { y0[j] = swish2(y0[j], h2); y1[j] = swish2(y1[j], h2); }
#pragma unroll
            for (int j = 0; j < 8; j += 2) {
                ull wlo, whi; lds2u64(wlo, whi, w3a + h * 128 + jh * 64 + j * 8);
                a30 = fma2(y0[j], wlo, a30); a30 = fma2(y0[j + 1], whi, a30);
                a31 = fma2(y1[j], wlo, a31); a31 = fma2(y1[j + 1], whi, a31);
            }
        }
        ull aloc0 = swish2(a30, h2);
        ull aloc1 = swish2(a31, h2);

        ull af0 = pack2(0.0f, 0.0f), af1 = af0;
        unsigned kh = kta + (h * 32) * 128;
#pragma unroll
        for (int cc = 0; cc < 32; cc += 4) {
            float4 q0 = *(const float4*)&Qs[(2 * ni) * 260 + h * 32 + cc];
            float4 q1 = *(const float4*)&Qs[(2 * ni + 1) * 260 + h * 32 + cc];
            ull k0 = lds1u64(kh + (cc + 0) * 128);
            ull k1 = lds1u64(kh + (cc + 1) * 128);
            ull k2 = lds1u64(kh + (cc + 2) * 128);
            ull k3 = lds1u64(kh + (cc + 3) * 128);
            af0 = fma2(k0, pack2(q0.x, q0.x), af0);
            af0 = fma2(k1, pack2(q0.y, q0.y), af0);
            af0 = fma2(k2, pack2(q0.z, q0.z), af0);
            af0 = fma2(k3, pack2(q0.w, q0.w), af0);
            af1 = fma2(k0, pack2(q1.x, q1.x), af1);
            af1 = fma2(k1, pack2(q1.y, q1.y), af1);
            af1 = fma2(k2, pack2(q1.z, q1.z), af1);
            af1 = fma2(k3, pack2(q1.w, q1.w), af1);
        }

        float a0, a1, l0, l1;
        float* pr = pre + ((size_t)(b * Hh + h) * Nn + nr0) * Nn;
        unpack2(af0, a0, a1); unpack2(aloc0, l0, l1);
        if (valid1)      *(float2*)&pr[cm0] = make_float2(l0 + a0 * 0.0625f, l1 + a1 * 0.0625f);
        else if (valid0) pr[cm0] = l0 + a0 * 0.0625f;
        unpack2(af1, a0, a1); unpack2(aloc1, l0, l1);
        if (valid1)      *(float2*)&pr[Nn + cm0] = make_float2(l0 + a0 * 0.0625f, l1 + a1 * 0.0625f);
        else if (valid0) pr[Nn + cm0] = l0 + a0 * 0.0625f;
    }
}

// ---------------- softmax + att@V, V tile staged in smem ----------------
#define SOFTMAX_SMEM_BYTES (18000 * 4)

__global__ __launch_bounds__(256)
void softmax_av_kernel(const float* __restrict__ pre,
                       const float* __restrict__ V,
                       const int* __restrict__ mcnt,
                       float* __restrict__ out) {
    extern __shared__ float sm2[];
    float*  att  = sm2;                      // [16][516]
    float*  Vs   = sm2 + 8256;               // [256][32]
    float4* part = (float4*)(sm2 + 16448);   // [3][16][8]
    float*  rinv = sm2 + 17984;              // [16]

    int b  = blockIdx.z;
    int h  = blockIdx.y;
    int n0 = blockIdx.x * 16;
    int t  = threadIdx.x;
    int row = t >> 4;
    int l16 = t & 15;

    int cnt  = mcnt[b];
    int jmax = (cnt + 63) >> 6;

    const float4* prow = (const float4*)(pre + ((size_t)(b * Hh + h) * Nn + n0 + row) * Nn);
    float* arow = att + row * 516;

    float mx = -3.0e38f;
    for (int j = 0; j < jmax; j++) {
        int i4 = j * 16 + l16;
        int m4 = i4 * 4;
        float4 v = prow[i4];
        if (m4 + 0 >= cnt) v.x = -1e38f;
        if (m4 + 1 >= cnt) v.y = -1e38f;
        if (m4 + 2 >= cnt) v.z = -1e38f;
        if (m4 + 3 >= cnt) v.w = -1e38f;
        *(float4*)&arow[m4] = v;
        mx = fmaxf(mx, fmaxf(fmaxf(v.x, v.y), fmaxf(v.z, v.w)));
    }
    mx = fmaxf(mx, __shfl_xor_sync(0xffffffff, mx, 1));
    mx = fmaxf(mx, __shfl_xor_sync(0xffffffff, mx, 2));
    mx = fmaxf(mx, __shfl_xor_sync(0xffffffff, mx, 4));
    mx = fmaxf(mx, __shfl_xor_sync(0xffffffff, mx, 8));

    float s = 0.0f;
    for (int j = 0; j < jmax; j++) {
        int m4 = (j * 16 + l16) * 4;
        float4 v = *(const float4*)&arow[m4];
        float4 e;
        e.x = __expf(v.x - mx); e.y = __expf(v.y - mx);
        e.z = __expf(v.z - mx); e.w = __expf(v.w - mx);
        s += e.x + e.y + e.z + e.w;
        *(float4*)&arow[m4] = e;
    }
    s += __shfl_xor_sync(0xffffffff, s, 1);
    s += __shfl_xor_sync(0xffffffff, s, 2);
    s += __shfl_xor_sync(0xffffffff, s, 4);
    s += __shfl_xor_sync(0xffffffff, s, 8);
    if (l16 == 0) rinv[row] = __fdividef(1.0f, s);

    int cntP = (cnt + 15) & ~15;
    int rp = t >> 5;
    int q  = (t >> 3) & 3;
    int dq = t & 7;
    int row0 = rp * 2;
    const float* a0row = att + (size_t)row0 * 516;
    const float* a1row = a0row + 516;
    const float* vbase = V + (size_t)b * Nn * Cc + h * Dd;

    float4 acc0 = make_float4(0.f, 0.f, 0.f, 0.f);
    float4 acc1 = make_float4(0.f, 0.f, 0.f, 0.f);

    for (int c0 = 0; c0 < cntP; c0 += 256) {
        __syncthreads();
#pragma unroll
        for (int pass = 0; pass < 8; pass++) {
            int lr = pass * 32 + (t >> 3);
            float4 v = *(const float4*)(vbase + (size_t)(c0 + lr) * Cc + ((t & 7) << 2));
            *(float4*)&Vs[lr * 32 + ((t & 7) << 2)] = v;
        }
        __syncthreads();

        int chunkLen = cntP - c0; if (chunkLen > 256) chunkLen = 256;
        int qLen = chunkLen >> 2;
        int mbase = q * qLen;
#pragma unroll 2
        for (int mm = 0; mm < qLen; mm += 4) {
            int ml = mbase + mm;
            int mg = c0 + ml;
            float4 a4 = *(const float4*)&a0row[mg];
            float4 b4 = *(const float4*)&a1row[mg];
            float4 v0 = *(const float4*)&Vs[(ml + 0) * 32 + (dq << 2)];
            float4 v1 = *(const float4*)&Vs[(ml + 1) * 32 + (dq << 2)];
            float4 v2 = *(const float4*)&Vs[(ml + 2) * 32 + (dq << 2)];
            float4 v3 = *(const float4*)&Vs[(ml + 3) * 32 + (dq << 2)];
            acc0.x = fmaf(a4.x, v0.x, acc0.x); acc0.y = fmaf(a4.x, v0.y, acc0.y);
            acc0.z = fmaf(a4.x, v0.z, acc0.z); acc0.w = fmaf(a4.x, v0.w, acc0.w);
            acc1.x = fmaf(b4.x, v0.x, acc1.x); acc1.y = fmaf(b4.x, v0.y, acc1.y);
            acc1.z = fmaf(b4.x, v0.z, acc1.z); acc1.w = fmaf(b4.x, v0.w, acc1.w);
            acc0.x = fmaf(a4.y, v1.x, acc0.x); acc0.y = fmaf(a4.y, v1.y, acc0.y);
            acc0.z = fmaf(a4.y, v1.z, acc0.z); acc0.w = fmaf(a4.y, v1.w, acc0.w);
            acc1.x = fmaf(b4.y, v1.x, acc1.x); acc1.y = fmaf(b4.y, v1.y, acc1.y);
            acc1.z = fmaf(b4.y, v1.z, acc1.z); acc1.w = fmaf(b4.y, v1.w, acc1.w);
            acc0.x = fmaf(a4.z, v2.x, acc0.x); acc0.y = fmaf(a4.z, v2.y, acc0.y);
            acc0.z = fmaf(a4.z, v2.z, acc0.z); acc0.w = fmaf(a4.z, v2.w, acc0.w);
            acc1.x = fmaf(b4.z, v2.x, acc1.x); acc1.y = fmaf(b4.z, v2.y, acc1.y);
            acc1.z = fmaf(b4.z, v2.z, acc1.z); acc1.w = fmaf(b4.z, v2.w, acc1.w);
            acc0.x = fmaf(a4.w, v3.x, acc0.x); acc0.y = fmaf(a4.w, v3.y, acc0.y);
            acc0.z = fmaf(a4.w, v3.z, acc0.z); acc0.w = fmaf(a4.w, v3.w, acc0.w);
            acc1.x = fmaf(b4.w, v3.x, acc1.x); acc1.y = fmaf(b4.w, v3.y, acc1.y);
            acc1.z = fmaf(b4.w, v3.z, acc1.z); acc1.w = fmaf(b4.w, v3.w, acc1.w);
        }
    }

    if (q > 0) {
        part[((q - 1) * 16 + row0) * 8 + dq] = acc0;
        part[((q - 1) * 16 + row0 + 1) * 8 + dq] = acc1;
    }
    __syncthreads();

    if (q == 0) {
        float iv0 = rinv[row0];
        float iv1 = rinv[row0 + 1];
#pragma unroll
        for (int pq = 0; pq < 3; pq++) {
            float4 p0 = part[(pq * 16 + row0) * 8 + dq];
            float4 p1 = part[(pq * 16 + row0 + 1) * 8 + dq];
            acc0.x += p0.x; acc0.y += p0.y; acc0.z += p0.z; acc0.w += p0.w;
            acc1.x += p1.x; acc1.y += p1.y; acc1.z += p1.z; acc1.w += p1.w;
        }
        acc0.x *= iv0; acc0.y *= iv0; acc0.z *= iv0; acc0.w *= iv0;
        acc1.x *= iv1; acc1.y *= iv1; acc1.z *= iv1; acc1.w *= iv1;
        *(float4*)&out[(size_t)(b * Nn + n0 + row0) * Cc + h * Dd + (dq << 2)] = acc0;
        *(float4*)&out[(size_t)(b * Nn + n0 + row0 + 1) * Cc + h * Dd + (dq << 2)] = acc1;
    }
}

// ---------------- launch ----------------
extern "C" void kernel_launch(void* const* d_in, const int* in_sizes, int n_in,
                              void* d_out, int out_size) {
    const float* pg = (const float*)d_in[0];
    const float* cs = (const float*)d_in[1];
    const float* qw = (const float*)d_in[2];
    const float* qb = (const float*)d_in[3];
    const float* kw = (const float*)d_in[4];
    const float* kb = (const float*)d_in[5];
    const float* iw = (const float*)d_in[6];
    const float* ib = (const float*)d_in[7];
    const float* ow = (const float*)d_in[8];
    const float* ob = (const float*)d_in[9];
    const float* w1 = (const float*)d_in[10];
    const float* b1 = (const float*)d_in[11];
    const float* w2 = (const float*)d_in[12];
    const float* b2 = (const float*)d_in[13];
    const float* w3 = (const float*)d_in[14];
    const float* b3 = (const float*)d_in[15];
    const int*  mask = (const int*)d_in[16];

    float *Qp, *Kp, *Vp, *Op, *Pp;
    int *MIp, *MPp, *MCp;
    cudaGetSymbolAddress((void**)&Qp, g_Q);
    cudaGetSymbolAddress((void**)&Kp, g_K);
    cudaGetSymbolAddress((void**)&Vp, g_V);
    cudaGetSymbolAddress((void**)&Op, g_O);
    cudaGetSymbolAddress((void**)&Pp, g_pre);
    cudaGetSymbolAddress((void**)&MIp, g_midx);
    cudaGetSymbolAddress((void**)&MPp, g_mpos);
    cudaGetSymbolAddress((void**)&MCp, g_mcnt);

    cudaFuncSetAttribute(logits_kernel,
                         cudaFuncAttributeMaxDynamicSharedMemorySize,
                         LOGITS_SMEM_BYTES);
    cudaFuncSetAttribute(softmax_av_kernel,
                         cudaFuncAttributeMaxDynamicSharedMemorySize,
                         SOFTMAX_SMEM_BYTES);

    const int M = Bn * Nn;   // 2048

    compact_mask_kernel<<<Bn, 512>>>(mask, MIp, MPp, MCp);

    gemm_qkv_kernel<<<dim3(Cc / 64, M / 64, 3), 256>>>(cs, qw, qb, kw, kb, iw, ib,
                                                       Qp, Kp, Vp, MPp);

    logits_kernel<<<dim3(Nn / 32, Nn / 16, Bn), 128, LOGITS_SMEM_BYTES>>>(
        pg, Qp, Kp, w1, b1, w2, b2, w3, b3, MIp, MCp, Pp);

    softmax_av_kernel<<<dim3(Nn / 16, Hh, Bn), 256, SOFTMAX_SMEM_BYTES>>>(
        Pp, Vp, MCp, Op);

    gemm_out_kernel<<<dim3(Cc / 64, M / 64), 256>>>(Op, ow, ob, (float*)d_out);
}

// round 15
// speedup vs baseline: 1.1307x; 1.0040x over previous
#include <cuda_runtime.h>
#include <math.h>

typedef unsigned long long ull;

#define Bn 4
#define Nn 512
#define Cc 256
#define Hh 8
#define Dd 32
#define DG 6
#define HID 16

// ---------------- scratch (device globals; no allocation) ----------------
__device__ float g_Q[Bn * Nn * Cc];
__device__ float g_K[Bn * Nn * Cc];   // row-compacted per batch
__device__ float g_V[Bn * Nn * Cc];   // row-compacted per batch (rows >= cnt stay 0)
__device__ float g_O[Bn * Nn * Cc];
__device__ float g_pre[(size_t)Bn * Hh * Nn * Nn];   // [b][h][n][cm] compacted cols
__device__ int   g_midx[Bn * Nn];                    // compacted -> real m
__device__ int   g_mpos[Bn * Nn];                    // real m -> compacted (or -1)
__device__ int   g_mcnt[Bn];                         // count per batch

// ---------------- packed f32x2 helpers ----------------
__device__ __forceinline__ ull pack2(float a, float b) {
    ull r; asm("mov.b64 %0, {%1,%2};" : "=l"(r) : "f"(a), "f"(b)); return r;
}
__device__ __forceinline__ void unpack2(ull v, float& a, float& b) {
    asm("mov.b64 {%0,%1}, %2;" : "=f"(a), "=f"(b) : "l"(v));
}
__device__ __forceinline__ ull fma2(ull a, ull b, ull c) {
    ull r; asm("fma.rn.f32x2 %0, %1, %2, %3;" : "=l"(r) : "l"(a), "l"(b), "l"(c)); return r;
}
__device__ __forceinline__ ull mul2(ull a, ull b) {
    ull r; asm("mul.rn.f32x2 %0, %1, %2;" : "=l"(r) : "l"(a), "l"(b)); return r;
}
__device__ __forceinline__ float tanh_ap(float x) {
    float r; asm("tanh.approx.f32 %0, %1;" : "=f"(r) : "f"(x)); return r;
}
__device__ __forceinline__ void lds2u64(ull& a, ull& b, unsigned addr) {
    asm volatile("ld.shared.v2.b64 {%0,%1}, [%2];" : "=l"(a), "=l"(b) : "r"(addr));
}
__device__ __forceinline__ ull lds1u64(unsigned addr) {
    ull a; asm volatile("ld.shared.b64 %0, [%1];" : "=l"(a) : "r"(addr)); return a;
}
__device__ __forceinline__ unsigned s2u(const void* p) {
    unsigned r;
    asm("{.reg .u64 t; cvta.to.shared.u64 t, %1; cvt.u32.u64 %0, t;}" : "=r"(r) : "l"(p));
    return r;
}
// swish(x) = 0.5x*tanh(0.5x) + 0.5x   (packed, 1 MUFU per lane)
__device__ __forceinline__ ull swish2(ull x, ull h2) {
    ull t = mul2(x, h2);
    float a, b; unpack2(t, a, b);
    ull th = pack2(tanh_ap(a), tanh_ap(b));
    return fma2(t, th, t);
}

// ---------------- mask compaction: one CTA per batch ----------------
__global__ void compact_mask_kernel(const int* __restrict__ mask,
                                    int* __restrict__ midx,
                                    int* __restrict__ mpos,
                                    int* __restrict__ mcnt) {
    __shared__ int wsum[16];
    int b = blockIdx.x;
    int t = threadIdx.x;            // 512 threads
    int lane = t & 31, wid = t >> 5;

    int v = mask[b * Nn + t] ? 1 : 0;
    unsigned bal = __ballot_sync(0xffffffff, v);
    int pre_in_warp = __popc(bal & ((1u << lane) - 1u));
    if (lane == 31) wsum[wid] = pre_in_warp + v;
    __syncthreads();
    if (t < 32) {
        int x = (t < 16) ? wsum[t] : 0;
        for (int off = 1; off < 16; off <<= 1) {
            int y = __shfl_up_sync(0xffffffff, x, off);
            if (lane >= off) x += y;
        }
        if (t < 16) wsum[t] = x;
    }
    __syncthreads();
    int base = (wid > 0 ? wsum[wid - 1] : 0);
    int p = base + pre_in_warp;
    mpos[b * Nn + t] = v ? p : -1;
    if (v) midx[b * Nn + p] = t;
    if (t == 511) mcnt[b] = wsum[15];
}

// ---------------- GEMM body: Y = X(Mx256) @ W(256x256) + bias ----------------
// 64x64 tile, 256 threads, 4x4 microtile, DOUBLE-BUFFERED smem (1 sync/iter).
// pos != nullptr: scatter output rows to compacted positions (skip masked).
__device__ __forceinline__ void gemm_body(const float* __restrict__ X,
                                          const float* __restrict__ W,
                                          const float* __restrict__ bias,
                                          float* __restrict__ Y,
                                          const int* __restrict__ pos) {
    __shared__ float As[2][16][68];   // As[buf][k][m]
    __shared__ float Bs[2][16][68];   // Bs[buf][k][n]

    int t  = threadIdx.x;
    int tx = t & 15;
    int ty = t >> 4;
    int m0 = blockIdx.y * 64;
    int n0 = blockIdx.x * 64;

    int xr = t >> 2;            // 0..63 (X row)
    int xc = (t & 3) << 2;      // 0,4,8,12
    int wr = t >> 4;            // 0..15
    int wc = (t & 15) << 2;     // 0..60
    const float* xptr = &X[(size_t)(m0 + xr) * Cc + xc];
    const float* wptr = &W[(size_t)wr * Cc + n0 + wc];

    float acc[4][4];
#pragma unroll
    for (int i = 0; i < 4; i++)
#pragma unroll
        for (int j = 0; j < 4; j++) acc[i][j] = 0.0f;

    // preload tile 0 into buffer 0
    {
        float4 xv = *(const float4*)xptr;
        float4 wv = *(const float4*)wptr;
        As[0][xc + 0][xr] = xv.x; As[0][xc + 1][xr] = xv.y;
        As[0][xc + 2][xr] = xv.z; As[0][xc + 3][xr] = xv.w;
        *(float4*)&Bs[0][wr][wc] = wv;
    }
    __syncthreads();

    int buf = 0;
#pragma unroll 1
    for (int k0 = 16; k0 < Cc; k0 += 16) {
        // issue next tile's loads
        float4 xv = *(const float4*)(xptr + k0);
        float4 wv = *(const float4*)(wptr + (size_t)k0 * Cc);

        // compute current buffer
#pragma unroll
        for (int k = 0; k < 16; k++) {
            float a[4], b[4];
            *(float4*)a = *(const float4*)&As[buf][k][ty << 2];
            *(float4*)b = *(const float4*)&Bs[buf][k][tx << 2];
#pragma unroll
            for (int i = 0; i < 4; i++)
#pragma unroll
                for (int j = 0; j < 4; j++) acc[i][j] = fmaf(a[i], b[j], acc[i][j]);
        }

        // store into the other buffer (no race with current reads)
        int nb = buf ^ 1;
        As[nb][xc + 0][xr] = xv.x; As[nb][xc + 1][xr] = xv.y;
        As[nb][xc + 2][xr] = xv.z; As[nb][xc + 3][xr] = xv.w;
        *(float4*)&Bs[nb][wr][wc] = wv;
        __syncthreads();
        buf = nb;
    }
    // last tile
#pragma unroll
    for (int k = 0; k < 16; k++) {
        float a[4], b[4];
        *(float4*)a = *(const float4*)&As[buf][k][ty << 2];
        *(float4*)b = *(const float4*)&Bs[buf][k][tx << 2];
#pragma unroll
        for (int i = 0; i < 4; i++)
#pragma unroll
            for (int j = 0; j < 4; j++) acc[i][j] = fmaf(a[i], b[j], acc[i][j]);
    }

    float4 bv = *(const float4*)&bias[n0 + (tx << 2)];
#pragma unroll
    for (int i = 0; i < 4; i++) {
        float4 o;
        o.x = acc[i][0] + bv.x; o.y = acc[i][1] + bv.y;
        o.z = acc[i][2] + bv.z; o.w = acc[i][3] + bv.w;
        int row = m0 + (ty << 2) + i;
        if (pos) {
            int p = pos[row];
            if (p < 0) continue;
            row = (row & ~(Nn - 1)) + p;
        }
        *(float4*)&Y[(size_t)row * Cc + n0 + (tx << 2)] = o;
    }
}

__global__ void gemm_qkv_kernel(const float* __restrict__ X,
                                const float* __restrict__ qw, const float* __restrict__ qb,
                                const float* __restrict__ kw, const float* __restrict__ kb,
                                const float* __restrict__ iw, const float* __restrict__ ib,
                                float* __restrict__ Qp, float* __restrict__ Kp,
                                float* __restrict__ Vp, const int* __restrict__ mpos) {
    if (blockIdx.z == 0)      gemm_body(X, qw, qb, Qp, nullptr);
    else if (blockIdx.z == 1) gemm_body(X, kw, kb, Kp, mpos);
    else                      gemm_body(X, iw, ib, Vp, mpos);
}

__global__ void gemm_out_kernel(const float* __restrict__ X,
                                const float* __restrict__ ow, const float* __restrict__ ob,
                                float* __restrict__ Yout) {
    gemm_body(X, ow, ob, Yout, nullptr);
}

// ---------------- logits over COMPACTED m (K compacted, pre compacted) ----------
#define LOGITS_SMEM_BYTES ((18768 + 32) * 4)

__global__ __launch_bounds__(128, 3)
void logits_kernel(const float* __restrict__ g,
                   const float* __restrict__ Q,
                   const float* __restrict__ K,
                   const float* __restrict__ w1, const float* __restrict__ b1,
                   const float* __restrict__ w2, const float* __restrict__ b2,
                   const float* __restrict__ w3, const float* __restrict__ b3,
                   const int* __restrict__ midx, const int* __restrict__ mcnt,
                   float* __restrict__ pre) {
    extern __shared__ float sm[];
    float*  Qs  = sm;
    float*  Kt  = sm + 4160;
    float2* w1d = (float2*)(sm + 12352);
    float2* w2d = (float2*)(sm + 13888);
    float2* w3d = (float2*)(sm + 17984);
    float2* b1d = (float2*)(sm + 18240);
    float2* b2d = (float2*)(sm + 18496);
    float2* b3d = (float2*)(sm + 18752);
    int*    mlist = (int*)(sm + 18768);

    int b  = blockIdx.z;
    int n0 = blockIdx.y * 16;
    int m0 = blockIdx.x * 32;           // compacted-column base
    int t  = threadIdx.x;

    int cnt = mcnt[b];
    if (m0 >= cnt) return;

    // real-m list for pairwise_g gather (clamped)
    if (t < 32) {
        int cm = m0 + t; if (cm > cnt - 1) cm = cnt - 1;
        mlist[t] = midx[b * Nn + cm];
    }

#pragma unroll
    for (int i = t; i < Hh * DG * HID; i += 128) { float v = w1[i]; w1d[i] = make_float2(v, v); }
#pragma unroll
    for (int i = t; i < Hh * HID * HID; i += 128){ float v = w2[i]; w2d[i] = make_float2(v, v); }
    {
        float v = w3[t]; w3d[t] = make_float2(v, v);
        float u = b1[t]; b1d[t] = make_float2(u, u);
        float z = b2[t]; b2d[t] = make_float2(z, z);
    }
    if (t < Hh) { float v = b3[t]; b3d[t] = make_float2(v, v); }

    // Q tile [16 n][256 c]
    {
        int r = t >> 3, c = (t & 7) << 5;
        const float* src = Q + (size_t)(b * Nn + n0 + r) * Cc + c;
#pragma unroll
        for (int v = 0; v < 8; v++)
            *(float4*)&Qs[r * 260 + c + v * 4] = *(const float4*)(src + v * 4);
    }
    // K tile transposed (K already row-compacted): Kt[c][cm-local]
#pragma unroll
    for (int bi = 0; bi < 4; bi++) {
        int blk = t + bi * 128;
        int bm = (blk & 7) << 2;
        int bc = (blk >> 3) << 2;
        int r0i = m0 + bm;     if (r0i > cnt - 1) r0i = cnt - 1;
        int r1i = m0 + bm + 1; if (r1i > cnt - 1) r1i = cnt - 1;
        int r2i = m0 + bm + 2; if (r2i > cnt - 1) r2i = cnt - 1;
        int r3i = m0 + bm + 3; if (r3i > cnt - 1) r3i = cnt - 1;
        float4 r0 = *(const float4*)&K[(size_t)(b * Nn + r0i) * Cc + bc];
        float4 r1 = *(const float4*)&K[(size_t)(b * Nn + r1i) * Cc + bc];
        float4 r2 = *(const float4*)&K[(size_t)(b * Nn + r2i) * Cc + bc];
        float4 r3 = *(const float4*)&K[(size_t)(b * Nn + r3i) * Cc + bc];
        *(float4*)&Kt[(bc + 0) * 32 + bm] = make_float4(r0.x, r1.x, r2.x, r3.x);
        *(float4*)&Kt[(bc + 1) * 32 + bm] = make_float4(r0.y, r1.y, r2.y, r3.y);
        *(float4*)&Kt[(bc + 2) * 32 + bm] = make_float4(r0.z, r1.z, r2.z, r3.z);
        *(float4*)&Kt[(bc + 3) * 32 + bm] = make_float4(r0.w, r1.w, r2.w, r3.w);
    }
    __syncthreads();

    int ni = t >> 4, mg = t & 15;
    int nr0 = n0 + 2 * ni;
    int cm0 = m0 + 2 * mg, cm1 = cm0 + 1;
    bool valid0 = cm0 < cnt, valid1 = cm1 < cnt;
    int mr0 = mlist[2 * mg];
    int mr1 = mlist[2 * mg + 1];

    // pairwise_g packed for both rows & both (gathered real) m's
    ull ga[6], gb[6];
    {
        const float* p00 = g + ((size_t)(b * Nn + nr0) * Nn + mr0) * DG;
        const float* p01 = g + ((size_t)(b * Nn + nr0) * Nn + mr1) * DG;
        const float* p10 = p00 + (size_t)Nn * DG;
        const float* p11 = p01 + (size_t)Nn * DG;
        float2 a0 = *(const float2*)(p00 + 0), a1 = *(const float2*)(p00 + 2), a2 = *(const float2*)(p00 + 4);
        float2 c0 = *(const float2*)(p01 + 0), c1 = *(const float2*)(p01 + 2), c2 = *(const float2*)(p01 + 4);
        ga[0] = pack2(a0.x, c0.x); ga[1] = pack2(a0.y, c0.y);
        ga[2] = pack2(a1.x, c1.x); ga[3] = pack2(a1.y, c1.y);
        ga[4] = pack2(a2.x, c2.x); ga[5] = pack2(a2.y, c2.y);
        float2 d0 = *(const float2*)(p10 + 0), d1 = *(const float2*)(p10 + 2), d2 = *(const float2*)(p10 + 4);
        float2 e0 = *(const float2*)(p11 + 0), e1 = *(const float2*)(p11 + 2), e2 = *(const float2*)(p11 + 4);
        gb[0] = pack2(d0.x, e0.x); gb[1] = pack2(d0.y, e0.y);
        gb[2] = pack2(d1.x, e1.x); gb[3] = pack2(d1.y, e1.y);
        gb[4] = pack2(d2.x, e2.x); gb[5] = pack2(d2.y, e2.y);
    }

    const ull h2 = pack2(0.5f, 0.5f);
    unsigned w1a = s2u(w1d), w2a = s2u(w2d), w3a = s2u(w3d);
    unsigned b1a = s2u(b1d), b2a = s2u(b2d), b3a = s2u(b3d);
    unsigned kta = s2u(Kt) + mg * 8;

#pragma unroll 1
    for (int h = 0; h < Hh; h++) {
        ull x0[16], x1[16];
        {
            unsigned ba = b1a + h * 128;
#pragma unroll
            for (int j = 0; j < 16; j += 2) {
                lds2u64(x0[j], x0[j + 1], ba + j * 8);
                x1[j] = x0[j]; x1[j + 1] = x0[j + 1];
            }
        }
#pragma unroll
        for (int k = 0; k < DG; k++) {
            unsigned wa = w1a + (h * DG + k) * 128;
#pragma unroll
            for (int j = 0; j < 16; j += 2) {
                ull wlo, whi; lds2u64(wlo, whi, wa + j * 8);
                x0[j]     = fma2(ga[k], wlo, x0[j]);
                x0[j + 1] = fma2(ga[k], whi, x0[j + 1]);
                x1[j]     = fma2(gb[k], wlo, x1[j]);
                x1[j + 1] = fma2(gb[k], whi, x1[j + 1]);
            }
        }
#pragma unroll
        for (int j = 0; j < 16; j++) { x0[j] = swish2(x0[j], h2); x1[j] = swish2(x1[j], h2); }

        ull a30 = lds1u64(b3a + h * 8);
        ull a31 = a30;
#pragma unroll
        for (int jh = 0; jh < 2; jh++) {
            ull y0[8], y1[8];
            unsigned ba = b2a + h * 128 + jh * 64;
#pragma unroll
            for (int j = 0; j < 8; j += 2) {
                lds2u64(y0[j], y0[j + 1], ba + j * 8);
                y1[j] = y0[j]; y1[j + 1] = y0[j + 1];
            }
#pragma unroll
            for (int k = 0; k < HID; k++) {
                unsigned wa = w2a + (h * HID + k) * 128 + jh * 64;
#pragma unroll
                for (int j = 0; j < 8; j += 2) {
                    ull wlo, whi; lds2u64(wlo, whi, wa + j * 8);
                    y0[j]     = fma2(x0[k], wlo, y0[j]);
                    y0[j + 1] = fma2(x0[k], whi, y0[j + 1]);
                    y1[j]     = fma2(x1[k], wlo, y1[j]);
                    y1[j + 1] = fma2(x1[k], whi, y1[j + 1]);
                }
            }
#pragma unroll
            for (int j = 0; j < 8; j++) { y0[j] = swish2(y0[j], h2); y1[j] = swish2(y1[j], h2); }
#pragma unroll
            for (int j = 0; j < 8; j += 2) {
                ull wlo, whi; lds2u64(wlo, whi, w3a + h * 128 + jh * 64 + j * 8);
                a30 = fma2(y0[j], wlo, a30); a30 = fma2(y0[j + 1], whi, a30);
                a31 = fma2(y1[j], wlo, a31); a31 = fma2(y1[j + 1], whi, a31);
            }
        }
        ull aloc0 = swish2(a30, h2);
        ull aloc1 = swish2(a31, h2);

        ull af0 = pack2(0.0f, 0.0f), af1 = af0;
        unsigned kh = kta + (h * 32) * 128;
#pragma unroll
        for (int cc = 0; cc < 32; cc += 4) {
            float4 q0 = *(const float4*)&Qs[(2 * ni) * 260 + h * 32 + cc];
            float4 q1 = *(const float4*)&Qs[(2 * ni + 1) * 260 + h * 32 + cc];
            ull k0 = lds1u64(kh + (cc + 0) * 128);
            ull k1 = lds1u64(kh + (cc + 1) * 128);
            ull k2 = lds1u64(kh + (cc + 2) * 128);
            ull k3 = lds1u64(kh + (cc + 3) * 128);
            af0 = fma2(k0, pack2(q0.x, q0.x), af0);
            af0 = fma2(k1, pack2(q0.y, q0.y), af0);
            af0 = fma2(k2, pack2(q0.z, q0.z), af0);
            af0 = fma2(k3, pack2(q0.w, q0.w), af0);
            af1 = fma2(k0, pack2(q1.x, q1.x), af1);
            af1 = fma2(k1, pack2(q1.y, q1.y), af1);
            af1 = fma2(k2, pack2(q1.z, q1.z), af1);
            af1 = fma2(k3, pack2(q1.w, q1.w), af1);
        }

        float a0, a1, l0, l1;
        float* pr = pre + ((size_t)(b * Hh + h) * Nn + nr0) * Nn;
        unpack2(af0, a0, a1); unpack2(aloc0, l0, l1);
        if (valid1)      *(float2*)&pr[cm0] = make_float2(l0 + a0 * 0.0625f, l1 + a1 * 0.0625f);
        else if (valid0) pr[cm0] = l0 + a0 * 0.0625f;
        unpack2(af1, a0, a1); unpack2(aloc1, l0, l1);
        if (valid1)      *(float2*)&pr[Nn + cm0] = make_float2(l0 + a0 * 0.0625f, l1 + a1 * 0.0625f);
        else if (valid0) pr[Nn + cm0] = l0 + a0 * 0.0625f;
    }
}

// ---------------- softmax + att@V, V tile staged in smem ----------------
#define SOFTMAX_SMEM_BYTES (18000 * 4)

__global__ __launch_bounds__(256)
void softmax_av_kernel(const float* __restrict__ pre,
                       const float* __restrict__ V,
                       const int* __restrict__ mcnt,
                       float* __restrict__ out) {
    extern __shared__ float sm2[];
    float*  att  = sm2;                      // [16][516]
    float*  Vs   = sm2 + 8256;               // [256][32]
    float4* part = (float4*)(sm2 + 16448);   // [3][16][8]
    float*  rinv = sm2 + 17984;              // [16]

    int b  = blockIdx.z;
    int h  = blockIdx.y;
    int n0 = blockIdx.x * 16;
    int t  = threadIdx.x;
    int row = t >> 4;
    int l16 = t & 15;

    int cnt  = mcnt[b];
    int jmax = (cnt + 63) >> 6;

    const float4* prow = (const float4*)(pre + ((size_t)(b * Hh + h) * Nn + n0 + row) * Nn);
    float* arow = att + row * 516;

    float mx = -3.0e38f;
    for (int j = 0; j < jmax; j++) {
        int i4 = j * 16 + l16;
        int m4 = i4 * 4;
        float4 v = prow[i4];
        if (m4 + 0 >= cnt) v.x = -1e38f;
        if (m4 + 1 >= cnt) v.y = -1e38f;
        if (m4 + 2 >= cnt) v.z = -1e38f;
        if (m4 + 3 >= cnt) v.w = -1e38f;
        *(float4*)&arow[m4] = v;
        mx = fmaxf(mx, fmaxf(fmaxf(v.x, v.y), fmaxf(v.z, v.w)));
    }
    mx = fmaxf(mx, __shfl_xor_sync(0xffffffff, mx, 1));
    mx = fmaxf(mx, __shfl_xor_sync(0xffffffff, mx, 2));
    mx = fmaxf(mx, __shfl_xor_sync(0xffffffff, mx, 4));
    mx = fmaxf(mx, __shfl_xor_sync(0xffffffff, mx, 8));

    float s = 0.0f;
    for (int j = 0; j < jmax; j++) {
        int m4 = (j * 16 + l16) * 4;
        float4 v = *(const float4*)&arow[m4];
        float4 e;
        e.x = __expf(v.x - mx); e.y = __expf(v.y - mx);
        e.z = __expf(v.z - mx); e.w = __expf(v.w - mx);
        s += e.x + e.y + e.z + e.w;
        *(float4*)&arow[m4] = e;
    }
    s += __shfl_xor_sync(0xffffffff, s, 1);
    s += __shfl_xor_sync(0xffffffff, s, 2);
    s += __shfl_xor_sync(0xffffffff, s, 4);
    s += __shfl_xor_sync(0xffffffff, s, 8);
    if (l16 == 0) rinv[row] = __fdividef(1.0f, s);

    int cntP = (cnt + 15) & ~15;
    int rp = t >> 5;
    int q  = (t >> 3) & 3;
    int dq = t & 7;
    int row0 = rp * 2;
    const float* a0row = att + (size_t)row0 * 516;
    const float* a1row = a0row + 516;
    const float* vbase = V + (size_t)b * Nn * Cc + h * Dd;

    float4 acc0 = make_float4(0.f, 0.f, 0.f, 0.f);
    float4 acc1 = make_float4(0.f, 0.f, 0.f, 0.f);

    for (int c0 = 0; c0 < cntP; c0 += 256) {
        __syncthreads();
#pragma unroll
        for (int pass = 0; pass < 8; pass++) {
            int lr = pass * 32 + (t >> 3);
            float4 v = *(const float4*)(vbase + (size_t)(c0 + lr) * Cc + ((t & 7) << 2));
            *(float4*)&Vs[lr * 32 + ((t & 7) << 2)] = v;
        }
        __syncthreads();

        int chunkLen = cntP - c0; if (chunkLen > 256) chunkLen = 256;
        int qLen = chunkLen >> 2;
        int mbase = q * qLen;
#pragma unroll 2
        for (int mm = 0; mm < qLen; mm += 4) {
            int ml = mbase + mm;
            int mg = c0 + ml;
            float4 a4 = *(const float4*)&a0row[mg];
            float4 b4 = *(const float4*)&a1row[mg];
            float4 v0 = *(const float4*)&Vs[(ml + 0) * 32 + (dq << 2)];
            float4 v1 = *(const float4*)&Vs[(ml + 1) * 32 + (dq << 2)];
            float4 v2 = *(const float4*)&Vs[(ml + 2) * 32 + (dq << 2)];
            float4 v3 = *(const float4*)&Vs[(ml + 3) * 32 + (dq << 2)];
            acc0.x = fmaf(a4.x, v0.x, acc0.x); acc0.y = fmaf(a4.x, v0.y, acc0.y);
            acc0.z = fmaf(a4.x, v0.z, acc0.z); acc0.w = fmaf(a4.x, v0.w, acc0.w);
            acc1.x = fmaf(b4.x, v0.x, acc1.x); acc1.y = fmaf(b4.x, v0.y, acc1.y);
            acc1.z = fmaf(b4.x, v0.z, acc1.z); acc1.w = fmaf(b4.x, v0.w, acc1.w);
            acc0.x = fmaf(a4.y, v1.x, acc0.x); acc0.y = fmaf(a4.y, v1.y, acc0.y);
            acc0.z = fmaf(a4.y, v1.z, acc0.z); acc0.w = fmaf(a4.y, v1.w, acc0.w);
            acc1.x = fmaf(b4.y, v1.x, acc1.x); acc1.y = fmaf(b4.y, v1.y, acc1.y);
            acc1.z = fmaf(b4.y, v1.z, acc1.z); acc1.w = fmaf(b4.y, v1.w, acc1.w);
            acc0.x = fmaf(a4.z, v2.x, acc0.x); acc0.y = fmaf(a4.z, v2.y, acc0.y);
            acc0.z = fmaf(a4.z, v2.z, acc0.z); acc0.w = fmaf(a4.z, v2.w, acc0.w);
            acc1.x = fmaf(b4.z, v2.x, acc1.x); acc1.y = fmaf(b4.z, v2.y, acc1.y);
            acc1.z = fmaf(b4.z, v2.z, acc1.z); acc1.w = fmaf(b4.z, v2.w, acc1.w);
            acc0.x = fmaf(a4.w, v3.x, acc0.x); acc0.y = fmaf(a4.w, v3.y, acc0.y);
            acc0.z = fmaf(a4.w, v3.z, acc0.z); acc0.w = fmaf(a4.w, v3.w, acc0.w);
            acc1.x = fmaf(b4.w, v3.x, acc1.x); acc1.y = fmaf(b4.w, v3.y, acc1.y);
            acc1.z = fmaf(b4.w, v3.z, acc1.z); acc1.w = fmaf(b4.w, v3.w, acc1.w);
        }
    }

    if (q > 0) {
        part[((q - 1) * 16 + row0) * 8 + dq] = acc0;
        part[((q - 1) * 16 + row0 + 1) * 8 + dq] = acc1;
    }
    __syncthreads();

    if (q == 0) {
        float iv0 = rinv[row0];
        float iv1 = rinv[row0 + 1];
#pragma unroll
        for (int pq = 0; pq < 3; pq++) {
            float4 p0 = part[(pq * 16 + row0) * 8 + dq];
            float4 p1 = part[(pq * 16 + row0 + 1) * 8 + dq];
            acc0.x += p0.x; acc0.y += p0.y; acc0.z += p0.z; acc0.w += p0.w;
            acc1.x += p1.x; acc1.y += p1.y; acc1.z += p1.z; acc1.w += p1.w;
        }
        acc0.x *= iv0; acc0.y *= iv0; acc0.z *= iv0; acc0.w *= iv0;
        acc1.x *= iv1; acc1.y *= iv1; acc1.z *= iv1; acc1.w *= iv1;
        *(float4*)&out[(size_t)(b * Nn + n0 + row0) * Cc + h * Dd + (dq << 2)] = acc0;
        *(float4*)&out[(size_t)(b * Nn + n0 + row0 + 1) * Cc + h * Dd + (dq << 2)] = acc1;
    }
}

// ---------------- launch ----------------
extern "C" void kernel_launch(void* const* d_in, const int* in_sizes, int n_in,
                              void* d_out, int out_size) {
    const float* pg = (const float*)d_in[0];
    const float* cs = (const float*)d_in[1];
    const float* qw = (const float*)d_in[2];
    const float* qb = (const float*)d_in[3];
    const float* kw = (const float*)d_in[4];
    const float* kb = (const float*)d_in[5];
    const float* iw = (const float*)d_in[6];
    const float* ib = (const float*)d_in[7];
    const float* ow = (const float*)d_in[8];
    const float* ob = (const float*)d_in[9];
    const float* w1 = (const float*)d_in[10];
    const float* b1 = (const float*)d_in[11];
    const float* w2 = (const float*)d_in[12];
    const float* b2 = (const float*)d_in[13];
    const float* w3 = (const float*)d_in[14];
    const float* b3 = (const float*)d_in[15];
    const int*  mask = (const int*)d_in[16];

    float *Qp, *Kp, *Vp, *Op, *Pp;
    int *MIp, *MPp, *MCp;
    cudaGetSymbolAddress((void**)&Qp, g_Q);
    cudaGetSymbolAddress((void**)&Kp, g_K);
    cudaGetSymbolAddress((void**)&Vp, g_V);
    cudaGetSymbolAddress((void**)&Op, g_O);
    cudaGetSymbolAddress((void**)&Pp, g_pre);
    cudaGetSymbolAddress((void**)&MIp, g_midx);
    cudaGetSymbolAddress((void**)&MPp, g_mpos);
    cudaGetSymbolAddress((void**)&MCp, g_mcnt);

    cudaFuncSetAttribute(logits_kernel,
                         cudaFuncAttributeMaxDynamicSharedMemorySize,
                         LOGITS_SMEM_BYTES);
    cudaFuncSetAttribute(softmax_av_kernel,
                         cudaFuncAttributeMaxDynamicSharedMemorySize,
                         SOFTMAX_SMEM_BYTES);

    const int M = Bn * Nn;   // 2048

    compact_mask_kernel<<<Bn, 512>>>(mask, MIp, MPp, MCp);

    gemm_qkv_kernel<<<dim3(Cc / 64, M / 64, 3), 256>>>(cs, qw, qb, kw, kb, iw, ib,
                                                       Qp, Kp, Vp, MPp);

    logits_kernel<<<dim3(Nn / 32, Nn / 16, Bn), 128, LOGITS_SMEM_BYTES>>>(
        pg, Qp, Kp, w1, b1, w2, b2, w3, b3, MIp, MCp, Pp);

    softmax_av_kernel<<<dim3(Nn / 16, Hh, Bn), 256, SOFTMAX_SMEM_BYTES>>>(
        Pp, Vp, MCp, Op);

    gemm_out_kernel<<<dim3(Cc / 64, M / 64), 256>>>(Op, ow, ob, (float*)d_out);
}

// round 16
// speedup vs baseline: 1.1593x; 1.0253x over previous
#include <cuda_runtime.h>
#include <math.h>

typedef unsigned long long ull;

#define Bn 4
#define Nn 512
#define Cc 256
#define Hh 8
#define Dd 32
#define DG 6
#define HID 16

// ---------------- scratch (device globals; no allocation) ----------------
__device__ float g_Q[Bn * Nn * Cc];
__device__ float g_K[Bn * Nn * Cc];   // row-compacted per batch (rows >= cnt stay 0)
__device__ float g_V[Bn * Nn * Cc];   // row-compacted per batch (rows >= cnt stay 0)
__device__ float g_O[Bn * Nn * Cc];
__device__ float g_pre[(size_t)Bn * Hh * Nn * Nn];    // A_feat/16  [b][h][n][cm]
__device__ float g_pre2[(size_t)Bn * Hh * Nn * Nn];   // A_loc      [b][h][n][cm]
__device__ int   g_midx[Bn * Nn];
__device__ int   g_mpos[Bn * Nn];
__device__ int   g_mcnt[Bn];

// ---------------- packed f32x2 helpers ----------------
__device__ __forceinline__ ull pack2(float a, float b) {
    ull r; asm("mov.b64 %0, {%1,%2};" : "=l"(r) : "f"(a), "f"(b)); return r;
}
__device__ __forceinline__ void unpack2(ull v, float& a, float& b) {
    asm("mov.b64 {%0,%1}, %2;" : "=f"(a), "=f"(b) : "l"(v));
}
__device__ __forceinline__ ull fma2(ull a, ull b, ull c) {
    ull r; asm("fma.rn.f32x2 %0, %1, %2, %3;" : "=l"(r) : "l"(a), "l"(b), "l"(c)); return r;
}
__device__ __forceinline__ ull mul2(ull a, ull b) {
    ull r; asm("mul.rn.f32x2 %0, %1, %2;" : "=l"(r) : "l"(a), "l"(b)); return r;
}
__device__ __forceinline__ float tanh_ap(float x) {
    float r; asm("tanh.approx.f32 %0, %1;" : "=f"(r) : "f"(x)); return r;
}
__device__ __forceinline__ void lds2u64(ull& a, ull& b, unsigned addr) {
    asm volatile("ld.shared.v2.b64 {%0,%1}, [%2];" : "=l"(a), "=l"(b) : "r"(addr));
}
__device__ __forceinline__ ull lds1u64(unsigned addr) {
    ull a; asm volatile("ld.shared.b64 %0, [%1];" : "=l"(a) : "r"(addr)); return a;
}
__device__ __forceinline__ unsigned s2u(const void* p) {
    unsigned r;
    asm("{.reg .u64 t; cvta.to.shared.u64 t, %1; cvt.u32.u64 %0, t;}" : "=r"(r) : "l"(p));
    return r;
}
// swish(x) = 0.5x*tanh(0.5x) + 0.5x
__device__ __forceinline__ ull swish2(ull x, ull h2) {
    ull t = mul2(x, h2);
    float a, b; unpack2(t, a, b);
    ull th = pack2(tanh_ap(a), tanh_ap(b));
    return fma2(t, th, t);
}

// ---------------- mask compaction ----------------
__global__ void compact_mask_kernel(const int* __restrict__ mask,
                                    int* __restrict__ midx,
                                    int* __restrict__ mpos,
                                    int* __restrict__ mcnt) {
    __shared__ int wsum[16];
    int b = blockIdx.x;
    int t = threadIdx.x;
    int lane = t & 31, wid = t >> 5;

    int v = mask[b * Nn + t] ? 1 : 0;
    unsigned bal = __ballot_sync(0xffffffff, v);
    int pre_in_warp = __popc(bal & ((1u << lane) - 1u));
    if (lane == 31) wsum[wid] = pre_in_warp + v;
    __syncthreads();
    if (t < 32) {
        int x = (t < 16) ? wsum[t] : 0;
        for (int off = 1; off < 16; off <<= 1) {
            int y = __shfl_up_sync(0xffffffff, x, off);
            if (lane >= off) x += y;
        }
        if (t < 16) wsum[t] = x;
    }
    __syncthreads();
    int base = (wid > 0 ? wsum[wid - 1] : 0);
    int p = base + pre_in_warp;
    mpos[b * Nn + t] = v ? p : -1;
    if (v) midx[b * Nn + p] = t;
    if (t == 511) mcnt[b] = wsum[15];
}

// ---------------- GEMM body: 64x64, double-buffered ----------------
__device__ __forceinline__ void gemm_body(const float* __restrict__ X,
                                          const float* __restrict__ W,
                                          const float* __restrict__ bias,
                                          float* __restrict__ Y,
                                          const int* __restrict__ pos) {
    __shared__ float As[2][16][68];
    __shared__ float Bs[2][16][68];

    int t  = threadIdx.x;
    int tx = t & 15;
    int ty = t >> 4;
    int m0 = blockIdx.y * 64;
    int n0 = blockIdx.x * 64;

    int xr = t >> 2;
    int xc = (t & 3) << 2;
    int wr = t >> 4;
    int wc = (t & 15) << 2;
    const float* xptr = &X[(size_t)(m0 + xr) * Cc + xc];
    const float* wptr = &W[(size_t)wr * Cc + n0 + wc];

    float acc[4][4];
#pragma unroll
    for (int i = 0; i < 4; i++)
#pragma unroll
        for (int j = 0; j < 4; j++) acc[i][j] = 0.0f;

    {
        float4 xv = *(const float4*)xptr;
        float4 wv = *(const float4*)wptr;
        As[0][xc + 0][xr] = xv.x; As[0][xc + 1][xr] = xv.y;
        As[0][xc + 2][xr] = xv.z; As[0][xc + 3][xr] = xv.w;
        *(float4*)&Bs[0][wr][wc] = wv;
    }
    __syncthreads();

    int buf = 0;
#pragma unroll 1
    for (int k0 = 16; k0 < Cc; k0 += 16) {
        float4 xv = *(const float4*)(xptr + k0);
        float4 wv = *(const float4*)(wptr + (size_t)k0 * Cc);

#pragma unroll
        for (int k = 0; k < 16; k++) {
            float a[4], b[4];
            *(float4*)a = *(const float4*)&As[buf][k][ty << 2];
            *(float4*)b = *(const float4*)&Bs[buf][k][tx << 2];
#pragma unroll
            for (int i = 0; i < 4; i++)
#pragma unroll
                for (int j = 0; j < 4; j++) acc[i][j] = fmaf(a[i], b[j], acc[i][j]);
        }

        int nb = buf ^ 1;
        As[nb][xc + 0][xr] = xv.x; As[nb][xc + 1][xr] = xv.y;
        As[nb][xc + 2][xr] = xv.z; As[nb][xc + 3][xr] = xv.w;
        *(float4*)&Bs[nb][wr][wc] = wv;
        __syncthreads();
        buf = nb;
    }
#pragma unroll
    for (int k = 0; k < 16; k++) {
        float a[4], b[4];
        *(float4*)a = *(const float4*)&As[buf][k][ty << 2];
        *(float4*)b = *(const float4*)&Bs[buf][k][tx << 2];
#pragma unroll
        for (int i = 0; i < 4; i++)
#pragma unroll
            for (int j = 0; j < 4; j++) acc[i][j] = fmaf(a[i], b[j], acc[i][j]);
    }

    float4 bv = *(const float4*)&bias[n0 + (tx << 2)];
#pragma unroll
    for (int i = 0; i < 4; i++) {
        float4 o;
        o.x = acc[i][0] + bv.x; o.y = acc[i][1] + bv.y;
        o.z = acc[i][2] + bv.z; o.w = acc[i][3] + bv.w;
        int row = m0 + (ty << 2) + i;
        if (pos) {
            int p = pos[row];
            if (p < 0) continue;
            row = (row & ~(Nn - 1)) + p;
        }
        *(float4*)&Y[(size_t)row * Cc + n0 + (tx << 2)] = o;
    }
}

__global__ void gemm_qkv_kernel(const float* __restrict__ X,
                                const float* __restrict__ qw, const float* __restrict__ qb,
                                const float* __restrict__ kw, const float* __restrict__ kb,
                                const float* __restrict__ iw, const float* __restrict__ ib,
                                float* __restrict__ Qp, float* __restrict__ Kp,
                                float* __restrict__ Vp, const int* __restrict__ mpos) {
    if (blockIdx.z == 0)      gemm_body(X, qw, qb, Qp, nullptr);
    else if (blockIdx.z == 1) gemm_body(X, kw, kb, Kp, mpos);
    else                      gemm_body(X, iw, ib, Vp, mpos);
}

__global__ void gemm_out_kernel(const float* __restrict__ X,
                                const float* __restrict__ ow, const float* __restrict__ ob,
                                float* __restrict__ Yout) {
    gemm_body(X, ow, ob, Yout, nullptr);
}

// ---------------- QK^T over compacted m: pre[b][h][n][cm] = dot/16 --------------
// grid (cm-tiles, n-tiles, b*h), 256 threads, 64x64 tile, K=32.
// K rows >= cnt are zeros in g_K -> A_feat 0 there (masked later).
__global__ __launch_bounds__(256)
void qk_kernel(const float* __restrict__ Q, const float* __restrict__ K,
               const int* __restrict__ mcnt, float* __restrict__ pre) {
    __shared__ float Qs[32][68];
    __shared__ float Ks[32][68];

    int bh = blockIdx.z;
    int b  = bh >> 3;
    int h  = bh & 7;
    int n0 = blockIdx.y * 64;
    int m0 = blockIdx.x * 64;
    int t  = threadIdx.x;

    if (m0 >= mcnt[b]) return;

#pragma unroll
    for (int i = 0; i < 2; i++) {
        int idx = t + i * 256;
        int r  = idx >> 3;
        int c4 = (idx & 7) << 2;
        float4 q = *(const float4*)&Q[(size_t)(b * Nn + n0 + r) * Cc + h * Dd + c4];
        Qs[c4 + 0][r] = q.x; Qs[c4 + 1][r] = q.y;
        Qs[c4 + 2][r] = q.z; Qs[c4 + 3][r] = q.w;
        float4 k = *(const float4*)&K[(size_t)(b * Nn + m0 + r) * Cc + h * Dd + c4];
        Ks[c4 + 0][r] = k.x; Ks[c4 + 1][r] = k.y;
        Ks[c4 + 2][r] = k.z; Ks[c4 + 3][r] = k.w;
    }
    __syncthreads();

    int tx = t & 15, ty = t >> 4;
    float acc[4][4];
#pragma unroll
    for (int i = 0; i < 4; i++)
#pragma unroll
        for (int j = 0; j < 4; j++) acc[i][j] = 0.0f;

#pragma unroll
    for (int k = 0; k < 32; k++) {
        float a[4], c[4];
        *(float4*)a = *(const float4*)&Qs[k][ty << 2];
        *(float4*)c = *(const float4*)&Ks[k][tx << 2];
#pragma unroll
        for (int i = 0; i < 4; i++)
#pragma unroll
            for (int j = 0; j < 4; j++) acc[i][j] = fmaf(a[i], c[j], acc[i][j]);
    }

    float* pr = pre + ((size_t)(b * Hh + h) * Nn + n0 + (ty << 2)) * Nn + m0 + (tx << 2);
#pragma unroll
    for (int i = 0; i < 4; i++) {
        float4 o;
        o.x = acc[i][0] * 0.0625f; o.y = acc[i][1] * 0.0625f;
        o.z = acc[i][2] * 0.0625f; o.w = acc[i][3] * 0.0625f;
        *(float4*)(pr + (size_t)i * Nn) = o;
    }
}

// ---------------- logits MLP only (slim, 4 CTAs/SM): pre2 = A_loc ----------------
__global__ __launch_bounds__(128, 4)
void logits_kernel(const float* __restrict__ g,
                   const float* __restrict__ w1, const float* __restrict__ b1,
                   const float* __restrict__ w2, const float* __restrict__ b2,
                   const float* __restrict__ w3, const float* __restrict__ b3,
                   const int* __restrict__ midx, const int* __restrict__ mcnt,
                   float* __restrict__ pre2) {
    __shared__ float2 w1d[Hh * DG * HID];
    __shared__ float2 w2d[Hh * HID * HID];
    __shared__ float2 w3d[Hh * HID];
    __shared__ float2 b1d[Hh * HID];
    __shared__ float2 b2d[Hh * HID];
    __shared__ float2 b3d[Hh];
    __shared__ int    mlist[32];

    int b  = blockIdx.z;
    int n0 = blockIdx.y * 16;
    int m0 = blockIdx.x * 32;
    int t  = threadIdx.x;

    int cnt = mcnt[b];
    if (m0 >= cnt) return;

    if (t < 32) {
        int cm = m0 + t; if (cm > cnt - 1) cm = cnt - 1;
        mlist[t] = midx[b * Nn + cm];
    }

#pragma unroll
    for (int i = t; i < Hh * DG * HID; i += 128) { float v = w1[i]; w1d[i] = make_float2(v, v); }
#pragma unroll
    for (int i = t; i < Hh * HID * HID; i += 128){ float v = w2[i]; w2d[i] = make_float2(v, v); }
    {
        float v = w3[t]; w3d[t] = make_float2(v, v);
        float u = b1[t]; b1d[t] = make_float2(u, u);
        float z = b2[t]; b2d[t] = make_float2(z, z);
    }
    if (t < Hh) { float v = b3[t]; b3d[t] = make_float2(v, v); }
    __syncthreads();

    int ni = t >> 4, mg = t & 15;
    int nr0 = n0 + 2 * ni;
    int cm0 = m0 + 2 * mg, cm1 = cm0 + 1;
    bool valid0 = cm0 < cnt, valid1 = cm1 < cnt;
    int mr0 = mlist[2 * mg];
    int mr1 = mlist[2 * mg + 1];

    ull ga[6], gb[6];
    {
        const float* p00 = g + ((size_t)(b * Nn + nr0) * Nn + mr0) * DG;
        const float* p01 = g + ((size_t)(b * Nn + nr0) * Nn + mr1) * DG;
        const float* p10 = p00 + (size_t)Nn * DG;
        const float* p11 = p01 + (size_t)Nn * DG;
        float2 a0 = *(const float2*)(p00 + 0), a1 = *(const float2*)(p00 + 2), a2 = *(const float2*)(p00 + 4);
        float2 c0 = *(const float2*)(p01 + 0), c1 = *(const float2*)(p01 + 2), c2 = *(const float2*)(p01 + 4);
        ga[0] = pack2(a0.x, c0.x); ga[1] = pack2(a0.y, c0.y);
        ga[2] = pack2(a1.x, c1.x); ga[3] = pack2(a1.y, c1.y);
        ga[4] = pack2(a2.x, c2.x); ga[5] = pack2(a2.y, c2.y);
        float2 d0 = *(const float2*)(p10 + 0), d1 = *(const float2*)(p10 + 2), d2 = *(const float2*)(p10 + 4);
        float2 e0 = *(const float2*)(p11 + 0), e1 = *(const float2*)(p11 + 2), e2 = *(const float2*)(p11 + 4);
        gb[0] = pack2(d0.x, e0.x); gb[1] = pack2(d0.y, e0.y);
        gb[2] = pack2(d1.x, e1.x); gb[3] = pack2(d1.y, e1.y);
        gb[4] = pack2(d2.x, e2.x); gb[5] = pack2(d2.y, e2.y);
    }

    const ull h2 = pack2(0.5f, 0.5f);
    unsigned w1a = s2u(w1d), w2a = s2u(w2d), w3a = s2u(w3d);
    unsigned b1a = s2u(b1d), b2a = s2u(b2d), b3a = s2u(b3d);

#pragma unroll 1
    for (int h = 0; h < Hh; h++) {
        ull x0[16], x1[16];
        {
            unsigned ba = b1a + h * 128;
#pragma unroll
            for (int j = 0; j < 16; j += 2) {
                lds2u64(x0[j], x0[j + 1], ba + j * 8);
                x1[j] = x0[j]; x1[j + 1] = x0[j + 1];
            }
        }
#pragma unroll
        for (int k = 0; k < DG; k++) {
            unsigned wa = w1a + (h * DG + k) * 128;
#pragma unroll
            for (int j = 0; j < 16; j += 2) {
                ull wlo, whi; lds2u64(wlo, whi, wa + j * 8);
                x0[j]     = fma2(ga[k], wlo, x0[j]);
                x0[j + 1] = fma2(ga[k], whi, x0[j + 1]);
                x1[j]     = fma2(gb[k], wlo, x1[j]);
                x1[j + 1] = fma2(gb[k], whi, x1[j + 1]);
            }
        }
#pragma unroll
        for (int j = 0; j < 16; j++) { x0[j] = swish2(x0[j], h2); x1[j] = swish2(x1[j], h2); }

        ull a30 = lds1u64(b3a + h * 8);
        ull a31 = a30;
#pragma unroll
        for (int jh = 0; jh < 2; jh++) {
            ull y0[8], y1[8];
            unsigned ba = b2a + h * 128 + jh * 64;
#pragma unroll
            for (int j = 0; j < 8; j += 2) {
                lds2u64(y0[j], y0[j + 1], ba + j * 8);
                y1[j] = y0[j]; y1[j + 1] = y0[j + 1];
            }
#pragma unroll
            for (int k = 0; k < HID; k++) {
                unsigned wa = w2a + (h * HID + k) * 128 + jh * 64;
#pragma unroll
                for (int j = 0; j < 8; j += 2) {
                    ull wlo, whi; lds2u64(wlo, whi, wa + j * 8);
                    y0[j]     = fma2(x0[k], wlo, y0[j]);
                    y0[j + 1] = fma2(x0[k], whi, y0[j + 1]);
                    y1[j]     = fma2(x1[k], wlo, y1[j]);
                    y1[j + 1] = fma2(x1[k], whi, y1[j + 1]);
                }
            }
#pragma unroll
            for (int j = 0; j < 8; j++) { y0[j] = swish2(y0[j], h2); y1[j] = swish2(y1[j], h2); }
#pragma unroll
            for (int j = 0; j < 8; j += 2) {
                ull wlo, whi; lds2u64(wlo, whi, w3a + h * 128 + jh * 64 + j * 8);
                a30 = fma2(y0[j], wlo, a30); a30 = fma2(y0[j + 1], whi, a30);
                a31 = fma2(y1[j], wlo, a31); a31 = fma2(y1[j + 1], whi, a31);
            }
        }
        ull aloc0 = swish2(a30, h2);
        ull aloc1 = swish2(a31, h2);

        float l0, l1;
        float* pr = pre2 + ((size_t)(b * Hh + h) * Nn + nr0) * Nn;
        unpack2(aloc0, l0, l1);
        if (valid1)      *(float2*)&pr[cm0] = make_float2(l0, l1);
        else if (valid0) pr[cm0] = l0;
        unpack2(aloc1, l0, l1);
        if (valid1)      *(float2*)&pr[Nn + cm0] = make_float2(l0, l1);
        else if (valid0) pr[Nn + cm0] = l0;
    }
}

// ---------------- softmax + att@V, V tile staged in smem (dual pre streams) -----
#define SOFTMAX_SMEM_BYTES (18000 * 4)

__global__ __launch_bounds__(256)
void softmax_av_kernel(const float* __restrict__ pre,
                       const float* __restrict__ pre2,
                       const float* __restrict__ V,
                       const int* __restrict__ mcnt,
                       float* __restrict__ out) {
    extern __shared__ float sm2[];
    float*  att  = sm2;                      // [16][516]
    float*  Vs   = sm2 + 8256;               // [256][32]
    float4* part = (float4*)(sm2 + 16448);   // [3][16][8]
    float*  rinv = sm2 + 17984;              // [16]

    int b  = blockIdx.z;
    int h  = blockIdx.y;
    int n0 = blockIdx.x * 16;
    int t  = threadIdx.x;
    int row = t >> 4;
    int l16 = t & 15;

    int cnt  = mcnt[b];
    int jmax = (cnt + 63) >> 6;

    size_t rowoff = ((size_t)(b * Hh + h) * Nn + n0 + row) * Nn;
    const float4* prow  = (const float4*)(pre + rowoff);
    const float4* prow2 = (const float4*)(pre2 + rowoff);
    float* arow = att + row * 516;

    float mx = -3.0e38f;
    for (int j = 0; j < jmax; j++) {
        int i4 = j * 16 + l16;
        int m4 = i4 * 4;
        float4 v = prow[i4];
        float4 w = prow2[i4];
        v.x += w.x; v.y += w.y; v.z += w.z; v.w += w.w;
        if (m4 + 0 >= cnt) v.x = -1e38f;
        if (m4 + 1 >= cnt) v.y = -1e38f;
        if (m4 + 2 >= cnt) v.z = -1e38f;
        if (m4 + 3 >= cnt) v.w = -1e38f;
        *(float4*)&arow[m4] = v;
        mx = fmaxf(mx, fmaxf(fmaxf(v.x, v.y), fmaxf(v.z, v.w)));
    }
    mx = fmaxf(mx, __shfl_xor_sync(0xffffffff, mx, 1));
    mx = fmaxf(mx, __shfl_xor_sync(0xffffffff, mx, 2));
    mx = fmaxf(mx, __shfl_xor_sync(0xffffffff, mx, 4));
    mx = fmaxf(mx, __shfl_xor_sync(0xffffffff, mx, 8));

    float s = 0.0f;
    for (int j = 0; j < jmax; j++) {
        int m4 = (j * 16 + l16) * 4;
        float4 v = *(const float4*)&arow[m4];
        float4 e;
        e.x = __expf(v.x - mx); e.y = __expf(v.y - mx);
        e.z = __expf(v.z - mx); e.w = __expf(v.w - mx);
        s += e.x + e.y + e.z + e.w;
        *(float4*)&arow[m4] = e;
    }
    s += __shfl_xor_sync(0xffffffff, s, 1);
    s += __shfl_xor_sync(0xffffffff, s, 2);
    s += __shfl_xor_sync(0xffffffff, s, 4);
    s += __shfl_xor_sync(0xffffffff, s, 8);
    if (l16 == 0) rinv[row] = __fdividef(1.0f, s);

    int cntP = (cnt + 15) & ~15;
    int rp = t >> 5;
    int q  = (t >> 3) & 3;
    int dq = t & 7;
    int row0 = rp * 2;
    const float* a0row = att + (size_t)row0 * 516;
    const float* a1row = a0row + 516;
    const float* vbase = V + (size_t)b * Nn * Cc + h * Dd;

    float4 acc0 = make_float4(0.f, 0.f, 0.f, 0.f);
    float4 acc1 = make_float4(0.f, 0.f, 0.f, 0.f);

    for (int c0 = 0; c0 < cntP; c0 += 256) {
        __syncthreads();
#pragma unroll
        for (int pass = 0; pass < 8; pass++) {
            int lr = pass * 32 + (t >> 3);
            float4 v = *(const float4*)(vbase + (size_t)(c0 + lr) * Cc + ((t & 7) << 2));
            *(float4*)&Vs[lr * 32 + ((t & 7) << 2)] = v;
        }
        __syncthreads();

        int chunkLen = cntP - c0; if (chunkLen > 256) chunkLen = 256;
        int qLen = chunkLen >> 2;
        int mbase = q * qLen;
#pragma unroll 2
        for (int mm = 0; mm < qLen; mm += 4) {
            int ml = mbase + mm;
            int mg = c0 + ml;
            float4 a4 = *(const float4*)&a0row[mg];
            float4 b4 = *(const float4*)&a1row[mg];
            float4 v0 = *(const float4*)&Vs[(ml + 0) * 32 + (dq << 2)];
            float4 v1 = *(const float4*)&Vs[(ml + 1) * 32 + (dq << 2)];
            float4 v2 = *(const float4*)&Vs[(ml + 2) * 32 + (dq << 2)];
            float4 v3 = *(const float4*)&Vs[(ml + 3) * 32 + (dq << 2)];
            acc0.x = fmaf(a4.x, v0.x, acc0.x); acc0.y = fmaf(a4.x, v0.y, acc0.y);
            acc0.z = fmaf(a4.x, v0.z, acc0.z); acc0.w = fmaf(a4.x, v0.w, acc0.w);
            acc1.x = fmaf(b4.x, v0.x, acc1.x); acc1.y = fmaf(b4.x, v0.y, acc1.y);
            acc1.z = fmaf(b4.x, v0.z, acc1.z); acc1.w = fmaf(b4.x, v0.w, acc1.w);
            acc0.x = fmaf(a4.y, v1.x, acc0.x); acc0.y = fmaf(a4.y, v1.y, acc0.y);
            acc0.z = fmaf(a4.y, v1.z, acc0.z); acc0.w = fmaf(a4.y, v1.w, acc0.w);
            acc1.x = fmaf(b4.y, v1.x, acc1.x); acc1.y = fmaf(b4.y, v1.y, acc1.y);
            acc1.z = fmaf(b4.y, v1.z, acc1.z); acc1.w = fmaf(b4.y, v1.w, acc1.w);
            acc0.x = fmaf(a4.z, v2.x, acc0.x); acc0.y = fmaf(a4.z, v2.y, acc0.y);
            acc0.z = fmaf(a4.z, v2.z, acc0.z); acc0.w = fmaf(a4.z, v2.w, acc0.w);
            acc1.x = fmaf(b4.z, v2.x, acc1.x); acc1.y = fmaf(b4.z, v2.y, acc1.y);
            acc1.z = fmaf(b4.z, v2.z, acc1.z); acc1.w = fmaf(b4.z, v2.w, acc1.w);
            acc0.x = fmaf(a4.w, v3.x, acc0.x); acc0.y = fmaf(a4.w, v3.y, acc0.y);
            acc0.z = fmaf(a4.w, v3.z, acc0.z); acc0.w = fmaf(a4.w, v3.w, acc0.w);
            acc1.x = fmaf(b4.w, v3.x, acc1.x); acc1.y = fmaf(b4.w, v3.y, acc1.y);
            acc1.z = fmaf(b4.w, v3.z, acc1.z); acc1.w = fmaf(b4.w, v3.w, acc1.w);
        }
    }

    if (q > 0) {
        part[((q - 1) * 16 + row0) * 8 + dq] = acc0;
        part[((q - 1) * 16 + row0 + 1) * 8 + dq] = acc1;
    }
    __syncthreads();

    if (q == 0) {
        float iv0 = rinv[row0];
        float iv1 = rinv[row0 + 1];
#pragma unroll
        for (int pq = 0; pq < 3; pq++) {
            float4 p0 = part[(pq * 16 + row0) * 8 + dq];
            float4 p1 = part[(pq * 16 + row0 + 1) * 8 + dq];
            acc0.x += p0.x; acc0.y += p0.y; acc0.z += p0.z; acc0.w += p0.w;
            acc1.x += p1.x; acc1.y += p1.y; acc1.z += p1.z; acc1.w += p1.w;
        }
        acc0.x *= iv0; acc0.y *= iv0; acc0.z *= iv0; acc0.w *= iv0;
        acc1.x *= iv1; acc1.y *= iv1; acc1.z *= iv1; acc1.w *= iv1;
        *(float4*)&out[(size_t)(b * Nn + n0 + row0) * Cc + h * Dd + (dq << 2)] = acc0;
        *(float4*)&out[(size_t)(b * Nn + n0 + row0 + 1) * Cc + h * Dd + (dq << 2)] = acc1;
    }
}

// ---------------- launch ----------------
extern "C" void kernel_launch(void* const* d_in, const int* in_sizes, int n_in,
                              void* d_out, int out_size) {
    const float* pg = (const float*)d_in[0];
    const float* cs = (const float*)d_in[1];
    const float* qw = (const float*)d_in[2];
    const float* qb = (const float*)d_in[3];
    const float* kw = (const float*)d_in[4];
    const float* kb = (const float*)d_in[5];
    const float* iw = (const float*)d_in[6];
    const float* ib = (const float*)d_in[7];
    const float* ow = (const float*)d_in[8];
    const float* ob = (const float*)d_in[9];
    const float* w1 = (const float*)d_in[10];
    const float* b1 = (const float*)d_in[11];
    const float* w2 = (const float*)d_in[12];
    const float* b2 = (const float*)d_in[13];
    const float* w3 = (const float*)d_in[14];
    const float* b3 = (const float*)d_in[15];
    const int*  mask = (const int*)d_in[16];

    float *Qp, *Kp, *Vp, *Op, *Pp, *P2p;
    int *MIp, *MPp, *MCp;
    cudaGetSymbolAddress((void**)&Qp, g_Q);
    cudaGetSymbolAddress((void**)&Kp, g_K);
    cudaGetSymbolAddress((void**)&Vp, g_V);
    cudaGetSymbolAddress((void**)&Op, g_O);
    cudaGetSymbolAddress((void**)&Pp, g_pre);
    cudaGetSymbolAddress((void**)&P2p, g_pre2);
    cudaGetSymbolAddress((void**)&MIp, g_midx);
    cudaGetSymbolAddress((void**)&MPp, g_mpos);
    cudaGetSymbolAddress((void**)&MCp, g_mcnt);

    cudaFuncSetAttribute(softmax_av_kernel,
                         cudaFuncAttributeMaxDynamicSharedMemorySize,
                         SOFTMAX_SMEM_BYTES);

    const int M = Bn * Nn;   // 2048

    compact_mask_kernel<<<Bn, 512>>>(mask, MIp, MPp, MCp);

    // A_loc MLP does not need Q/K -> launch first for overlap with qkv tail
    logits_kernel<<<dim3(Nn / 32, Nn / 16, Bn), 128>>>(
        pg, w1, b1, w2, b2, w3, b3, MIp, MCp, P2p);

    gemm_qkv_kernel<<<dim3(Cc / 64, M / 64, 3), 256>>>(cs, qw, qb, kw, kb, iw, ib,
                                                       Qp, Kp, Vp, MPp);

    qk_kernel<<<dim3(Nn / 64, Nn / 64, Bn * Hh), 256>>>(Qp, Kp, MCp, Pp);

    softmax_av_kernel<<<dim3(Nn / 16, Hh, Bn), 256, SOFTMAX_SMEM_BYTES>>>(
        Pp, P2p, Vp, MCp, Op);

    gemm_out_kernel<<<dim3(Cc / 64, M / 64), 256>>>(Op, ow, ob, (float*)d_out);
}